// round 12
// baseline (speedup 1.0000x reference)
#include <cuda_runtime.h>
#include <cuda_fp16.h>
#include <math.h>
#include <stdint.h>

// ---------------- problem constants ----------------
#define BATCH   64
#define NTOK    197
#define DIMC    768
#define HEADS   12
#define DHEAD   64
#define MROWS   (BATCH * NTOK)          // 12608
#define FDIM    (DIMC * 4)              // 3072
#define EPSLN   1e-6f

#define W_QKV_OFF  0
#define W_PROJ_OFF (3 * DIMC * DIMC)
#define W_FF1_OFF  (W_PROJ_OFF + DIMC * DIMC)
#define W_FF2_OFF  (W_FF1_OFF + FDIM * DIMC)
#define W_TOTAL    (W_FF2_OFF + DIMC * FDIM)

// ---------------- scratch (device globals, no allocation) ----------------
__device__ __half g_h  [MROWS * DIMC];                 // LN out (fp16)
__device__ __half g_q  [BATCH * HEADS * NTOK * DHEAD]; // q + cq (fp16)
__device__ __half g_k  [BATCH * HEADS * NTOK * DHEAD];
__device__ __half g_v  [BATCH * HEADS * NTOK * DHEAD];
__device__ float  g_cq [BATCH * DIMC];
__device__ float  g_ck [BATCH * DIMC];
__device__ __half g_o  [MROWS * DIMC];                 // attn out (fp16)
__device__ float  g_x1 [MROWS * DIMC];                 // x + attn branch (fp32)
__device__ __half g_ff [MROWS * FDIM];                 // gelu(ff1) (fp16)
__device__ __half g_wts[W_TOTAL];                      // fp16 weights

// ================= helpers =================
__device__ __forceinline__ void mma_f16(float* d, const uint32_t* a, const uint32_t* b) {
    asm volatile(
        "mma.sync.aligned.m16n8k16.row.col.f32.f16.f16.f32 "
        "{%0,%1,%2,%3}, {%4,%5,%6,%7}, {%8,%9}, {%0,%1,%2,%3};"
        : "+f"(d[0]), "+f"(d[1]), "+f"(d[2]), "+f"(d[3])
        : "r"(a[0]), "r"(a[1]), "r"(a[2]), "r"(a[3]), "r"(b[0]), "r"(b[1]));
}
__device__ __forceinline__ void ldsm_x4(uint32_t* r, uint32_t addr) {
    asm volatile("ldmatrix.sync.aligned.m8n8.x4.shared.b16 {%0,%1,%2,%3}, [%4];"
                 : "=r"(r[0]), "=r"(r[1]), "=r"(r[2]), "=r"(r[3]) : "r"(addr));
}
__device__ __forceinline__ uint32_t smem_u32(const void* p) {
    uint32_t a;
    asm("{ .reg .u64 t; cvta.to.shared.u64 t, %1; cvt.u32.u64 %0, t; }" : "=r"(a) : "l"(p));
    return a;
}
__device__ __forceinline__ void cpa16(uint32_t dst, const void* src, int sz) {
    asm volatile("cp.async.cg.shared.global [%0], [%1], 16, %2;" :: "r"(dst), "l"(src), "r"(sz));
}
#define CP_COMMIT asm volatile("cp.async.commit_group;" ::: "memory")
#define CP_WAIT0  asm volatile("cp.async.wait_group 0;" ::: "memory")
#define CP_WAIT1  asm volatile("cp.async.wait_group 1;" ::: "memory")

// fast exact-GELU via Abramowitz-Stegun 7.1.26 erf (|abs err| <= 1.5e-7)
__device__ __forceinline__ float fast_gelu(float v) {
    float z = fabsf(v) * 0.70710678118654752f;
    float t = __fdividef(1.0f, fmaf(0.3275911f, z, 1.0f));
    float poly = t * fmaf(t, fmaf(t, fmaf(t, fmaf(t, 1.061405429f, -1.453152027f),
                         1.421413741f), -0.284496736f), 0.254829592f);
    float er = 1.0f - poly * __expf(-z * z);
    er = copysignf(er, v);
    return 0.5f * v * (1.0f + er);
}

// ================= merged weight pre-conversion fp32 -> fp16 =================
#define N4_QKV  (3 * DIMC * DIMC / 4)
#define N4_PROJ (DIMC * DIMC / 4)
#define N4_FF1  (FDIM * DIMC / 4)
#define N4_TOT  (W_TOTAL / 4)
__global__ __launch_bounds__(256) void round_all_kernel(const float* __restrict__ qkv,
                                                        const float* __restrict__ proj,
                                                        const float* __restrict__ ff1,
                                                        const float* __restrict__ ff2,
                                                        __half* __restrict__ dst)
{
    int i = blockIdx.x * 256 + threadIdx.x;
    if (i >= N4_TOT) return;
    const float* src;
    int j = i;
    if (j < N4_QKV) src = qkv;
    else if ((j -= N4_QKV) < N4_PROJ) src = proj;
    else if ((j -= N4_PROJ) < N4_FF1) src = ff1;
    else { j -= N4_FF1; src = ff2; }
    float4 v = ((const float4*)src)[j];
    ((__half2*)dst)[2 * i]     = __floats2half2_rn(v.x, v.y);
    ((__half2*)dst)[2 * i + 1] = __floats2half2_rn(v.z, v.w);
}

// ================= fp16 mma GEMM, 256x128 tile, TBK=64, 512 thr, 3-stage =================
// MODE 0: QKV scatter (+cq/ck) -> half q/k/v, MODE 1: proj + resid -> fp32,
// MODE 2: ff1 + gelu -> half g_ff, MODE 3: ff2 + resid -> fp32 out
#define TBM 256
#define TBN 128
#define TBK 64
#define NTHR 512
#define HPAD 72
#define ABUF_A (TBM * HPAD * 2)          // 36864 B
#define ABUF_B (TBN * HPAD * 2)          // 18432 B
#define STG_BYTES (ABUF_A + ABUF_B)      // 55296 B
#define TC_SMEM (3 * STG_BYTES)          // 165888 B -> 1 CTA/SM, 16 warps

template<int MODE>
__global__ __launch_bounds__(NTHR, 1)
void tc_gemm(const __half* __restrict__ A, const __half* __restrict__ W,
             const float* __restrict__ bias, const float* __restrict__ resid,
             float* __restrict__ out, __half* __restrict__ hout, int M, int K)
{
    extern __shared__ char smem[];
    const uint32_t sb32 = smem_u32(smem);
    const int tid = threadIdx.x;
    const int wid = tid >> 5, lane = tid & 31;
    const int qr = lane >> 2, qc = lane & 3;
    const int wm = wid >> 2, wn = wid & 3;          // 4 x 4 warp grid
    const int m0 = blockIdx.y * TBM, n0 = blockIdx.x * TBN;

    // A staging: 512 threads cover 256 rows x 64 halves
    const int sr  = tid >> 1;
    const int sub = tid & 1;
    const int aok = ((m0 + sr) < M) ? 16 : 0;
    const __half* ap = A + (size_t)(m0 + sr) * K + sub * 32;
    const uint32_t da = sb32 + (sr * HPAD + sub * 32) * 2;
    // B staging: 512 threads cover 128 rows x 64 halves
    const int srb  = tid >> 2;
    const int subb = tid & 3;
    const __half* bp = W + (size_t)(n0 + srb) * K + subb * 16;
    const uint32_t db = sb32 + ABUF_A + (srb * HPAD + subb * 16) * 2;

    const int a_row  = (lane & 15);
    const int a_koff = (lane >> 4) << 3;
    const int b_row  = (lane & 7) + ((lane >> 4) << 3);
    const int b_koff = ((lane >> 3) & 1) << 3;
    uint32_t aoff[4], boff[2];
    #pragma unroll
    for (int mt = 0; mt < 4; mt++)
        aoff[mt] = ((wm * 64 + mt * 16 + a_row) * HPAD + a_koff) * 2;
    #pragma unroll
    for (int np = 0; np < 2; np++)
        boff[np] = ABUF_A + ((wn * 32 + np * 16 + b_row) * HPAD + b_koff) * 2;

    float acc[4][4][4];
    #pragma unroll
    for (int i = 0; i < 4; i++)
        #pragma unroll
        for (int j = 0; j < 4; j++)
            #pragma unroll
            for (int t = 0; t < 4; t++) acc[i][j][t] = 0.f;

    const int NC = K / TBK;

    // prologue: stages 0 and 1
    #pragma unroll
    for (int s = 0; s < 2; s++) {
        const uint32_t so = s * STG_BYTES;
        const int kk = s * TBK;
        #pragma unroll
        for (int q = 0; q < 4; q++) cpa16(da + so + q * 16, ap + kk + q * 8, aok);
        #pragma unroll
        for (int q = 0; q < 2; q++) cpa16(db + so + q * 16, bp + kk + q * 8, 16);
        CP_COMMIT;
    }

    for (int c = 0; c < NC; c++) {
        if (c + 1 < NC) { CP_WAIT1; } else { CP_WAIT0; }
        __syncthreads();        // all warps done with chunk c-1 -> slot (c+2)%3 free
        if (c + 2 < NC) {
            const uint32_t so = ((c + 2) % 3) * STG_BYTES;
            const int kk = (c + 2) * TBK;
            #pragma unroll
            for (int q = 0; q < 4; q++) cpa16(da + so + q * 16, ap + kk + q * 8, aok);
            #pragma unroll
            for (int q = 0; q < 2; q++) cpa16(db + so + q * 16, bp + kk + q * 8, 16);
            CP_COMMIT;
        }

        const uint32_t sbase = sb32 + (c % 3) * STG_BYTES;
        #pragma unroll
        for (int ks = 0; ks < 4; ks++) {
            const uint32_t kb = sbase + (ks * 16) * 2;
            uint32_t afr[4][4], bfr[4][2];
            #pragma unroll
            for (int mt = 0; mt < 4; mt++)
                ldsm_x4(afr[mt], kb + aoff[mt]);
            #pragma unroll
            for (int np = 0; np < 2; np++) {
                uint32_t r[4];
                ldsm_x4(r, kb + boff[np]);
                bfr[2 * np][0] = r[0]; bfr[2 * np][1] = r[1];
                bfr[2 * np + 1][0] = r[2]; bfr[2 * np + 1][1] = r[3];
            }
            #pragma unroll
            for (int mt = 0; mt < 4; mt++)
                #pragma unroll
                for (int nt = 0; nt < 4; nt++)
                    mma_f16(acc[mt][nt], afr[mt], bfr[nt]);
        }
    }

    // ---- epilogue: fused stores ----
    #pragma unroll
    for (int mt = 0; mt < 4; mt++) {
        int mA = m0 + wm * 64 + mt * 16 + qr;
        #pragma unroll
        for (int nt = 0; nt < 4; nt++) {
            int col = n0 + wn * 32 + nt * 8 + 2 * qc;
            float2 b2 = *(const float2*)&bias[col];
            #pragma unroll
            for (int half = 0; half < 2; half++) {
                int m = mA + half * 8;
                if (m >= M) continue;
                float v0 = acc[mt][nt][half * 2 + 0] + b2.x;
                float v1 = acc[mt][nt][half * 2 + 1] + b2.y;
                if (MODE == 0) {
                    int which = col / DIMC;
                    int r = col - which * DIMC;
                    int bI = m / NTOK, nI = m - bI * NTOK;
                    int h = r >> 6, d = r & 63;
                    __half* dst;
                    if (which == 0) {
                        float2 c2 = *(const float2*)&g_cq[bI * DIMC + r];
                        v0 += c2.x; v1 += c2.y; dst = g_q;
                    } else if (which == 1) {
                        float2 c2 = *(const float2*)&g_ck[bI * DIMC + r];
                        v0 += c2.x; v1 += c2.y; dst = g_k;
                    } else dst = g_v;
                    *(__half2*)&dst[((size_t)(bI * HEADS + h) * NTOK + nI) * DHEAD + d] =
                        __floats2half2_rn(v0, v1);
                } else if (MODE == 1 || MODE == 3) {
                    size_t ix = (size_t)m * DIMC + col;
                    float2 r2 = *(const float2*)&resid[ix];
                    *(float2*)&out[ix] = make_float2(v0 + r2.x, v1 + r2.y);
                } else { // MODE 2: fast gelu -> half g_ff
                    v0 = fast_gelu(v0);
                    v1 = fast_gelu(v1);
                    *(__half2*)&hout[(size_t)m * FDIM + col] = __floats2half2_rn(v0, v1);
                }
            }
        }
    }
}

// ================= fused attention: 1 CTA per (b,h), 4 q-blocks, fp16 mma =================
#define ATTW 16
#define QH_STR 72
#define KH_STR 72
#define VT_STR 216
#define PH_STR 216
#define AS_STR 212
#define SM_Q  0
#define SM_K  9216
#define SM_VT 39168
#define SM_P  66816
#define SM_S  94464
#define ATT_SMEM 148736

__global__ __launch_bounds__(32 * ATTW, 1) void attn_kernel()
{
    extern __shared__ char sm[];
    const uint32_t sb = smem_u32(sm);
    __half* Qs = (__half*)(sm + SM_Q);
    __half* Ks = (__half*)(sm + SM_K);
    __half* Vt = (__half*)(sm + SM_VT);
    __half* Ps = (__half*)(sm + SM_P);
    float*  Ss = (float*)(sm + SM_S);

    const int tid = threadIdx.x;
    const int wid = tid >> 5, lane = tid & 31;
    const int qr = lane >> 2, qc = lane & 3;
    const int bh = blockIdx.x;
    const int b = bh / HEADS, h = bh - (bh / HEADS) * HEADS;

    const __half* Qg = g_q + (size_t)bh * NTOK * DHEAD;
    const __half* Kg = g_k + (size_t)bh * NTOK * DHEAD;
    const __half* Vg = g_v + (size_t)bh * NTOK * DHEAD;

    // ---- load K (208x64, zero-padded) and V transposed (once per head) ----
    for (int idx = tid; idx < 208 * 8; idx += 32 * ATTW) {
        int r = idx >> 3, c8 = (idx & 7) * 8;
        uint4 v = make_uint4(0u, 0u, 0u, 0u);
        if (r < NTOK) v = *(const uint4*)&Kg[r * DHEAD + c8];
        *(uint4*)&Ks[r * KH_STR + c8] = v;
    }
    for (int idx = tid; idx < 208 * 8; idx += 32 * ATTW) {
        int key = idx >> 3, g = idx & 7, d8 = g * 8;
        __half vals[8];
        uint4 v = make_uint4(0u, 0u, 0u, 0u);
        if (key < NTOK) v = *(const uint4*)&Vg[key * DHEAD + d8];
        *(uint4*)vals = v;
        #pragma unroll
        for (int j = 0; j < 8; j++) {
            int jj = (j + g) & 7;
            Vt[(d8 + jj) * VT_STR + key] = vals[jj];
        }
    }

    const int a_row  = (lane & 15);
    const int a_koff = (lane >> 4) << 3;
    const int b_row  = (lane & 7) + ((lane >> 4) << 3);
    const int b_koff = ((lane >> 3) & 1) << 3;

    for (int blk = 0; blk < 4; blk++) {
        const int m0 = blk * 64;
        // ---- load Q block (64x64) ----
        {
            int r = tid >> 3, c8 = (tid & 7) * 8;
            int gr = m0 + r;
            uint4 v = make_uint4(0u, 0u, 0u, 0u);
            if (gr < NTOK) v = *(const uint4*)&Qg[gr * DHEAD + c8];
            *(uint4*)&Qs[r * QH_STR + c8] = v;
        }
        __syncthreads();    // K/V (first iter) and Q visible; prev PV done

        // ---- S = Q K^T * 0.125 ----
        for (int t = wid; t < 52; t += ATTW) {
            int mt = t & 3, kp = t >> 2;
            float acc0[4] = {0.f, 0.f, 0.f, 0.f};
            float acc1[4] = {0.f, 0.f, 0.f, 0.f};
            #pragma unroll
            for (int ks = 0; ks < 4; ks++) {
                uint32_t a[4], r[4];
                ldsm_x4(a, sb + SM_Q + (uint32_t)((mt * 16 + a_row) * QH_STR + ks * 16 + a_koff) * 2);
                ldsm_x4(r, sb + SM_K + (uint32_t)((kp * 16 + b_row) * KH_STR + ks * 16 + b_koff) * 2);
                uint32_t b0[2] = {r[0], r[1]}, b1[2] = {r[2], r[3]};
                mma_f16(acc0, a, b0);
                mma_f16(acc1, a, b1);
            }
            int r0 = mt * 16 + qr;
            int c0 = kp * 16 + 2 * qc;
            Ss[r0 * AS_STR + c0]            = acc0[0] * 0.125f;
            Ss[r0 * AS_STR + c0 + 1]        = acc0[1] * 0.125f;
            Ss[(r0 + 8) * AS_STR + c0]      = acc0[2] * 0.125f;
            Ss[(r0 + 8) * AS_STR + c0 + 1]  = acc0[3] * 0.125f;
            Ss[r0 * AS_STR + c0 + 8]        = acc1[0] * 0.125f;
            Ss[r0 * AS_STR + c0 + 9]        = acc1[1] * 0.125f;
            Ss[(r0 + 8) * AS_STR + c0 + 8]  = acc1[2] * 0.125f;
            Ss[(r0 + 8) * AS_STR + c0 + 9]  = acc1[3] * 0.125f;
        }
        __syncthreads();

        // ---- row softmax -> P (half) ----
        #pragma unroll
        for (int rr = 0; rr < 4; rr++) {
            int r = wid * 4 + rr;
            float vbuf[7];
            float mx = -1e30f;
            #pragma unroll
            for (int t = 0; t < 7; t++) {
                int col = lane + 32 * t;
                float v = (col < NTOK) ? Ss[r * AS_STR + col] : -1e30f;
                vbuf[t] = v;
                mx = fmaxf(mx, v);
            }
            #pragma unroll
            for (int o = 16; o > 0; o >>= 1)
                mx = fmaxf(mx, __shfl_xor_sync(0xffffffffu, mx, o));
            float sum = 0.f;
            #pragma unroll
            for (int t = 0; t < 7; t++) {
                int col = lane + 32 * t;
                float e = (col < NTOK) ? expf(vbuf[t] - mx) : 0.f;
                vbuf[t] = e;
                sum += e;
            }
            #pragma unroll
            for (int o = 16; o > 0; o >>= 1)
                sum += __shfl_xor_sync(0xffffffffu, sum, o);
            float inv = 1.0f / sum;
            #pragma unroll
            for (int t = 0; t < 7; t++) {
                int col = lane + 32 * t;
                if (col < 208)
                    Ps[r * PH_STR + col] = __float2half_rn((col < NTOK) ? vbuf[t] * inv : 0.f);
            }
        }
        __syncthreads();

        // ---- O = P V : one 16x16 output tile per warp ----
        {
            const int mt = wid & 3, np = wid >> 2;
            float acc0[4] = {0.f, 0.f, 0.f, 0.f};
            float acc1[4] = {0.f, 0.f, 0.f, 0.f};
            #pragma unroll
            for (int ks = 0; ks < 13; ks++) {
                uint32_t a[4], r[4];
                ldsm_x4(a, sb + SM_P  + (uint32_t)((mt * 16 + a_row) * PH_STR + ks * 16 + a_koff) * 2);
                ldsm_x4(r, sb + SM_VT + (uint32_t)((np * 16 + b_row) * VT_STR + ks * 16 + b_koff) * 2);
                uint32_t b0[2] = {r[0], r[1]}, b1[2] = {r[2], r[3]};
                mma_f16(acc0, a, b0);
                mma_f16(acc1, a, b1);
            }
            #pragma unroll
            for (int hf = 0; hf < 2; hf++) {
                int gr = m0 + mt * 16 + qr + hf * 8;
                if (gr < NTOK) {
                    size_t base = (size_t)(b * NTOK + gr) * DIMC + h * DHEAD + np * 16 + 2 * qc;
                    *(__half2*)&g_o[base]     = __floats2half2_rn(acc0[hf * 2], acc0[hf * 2 + 1]);
                    *(__half2*)&g_o[base + 8] = __floats2half2_rn(acc1[hf * 2], acc1[hf * 2 + 1]);
                }
            }
        }
    }
}

// ---------------- layernorm (fp16 output) ----------------
__global__ __launch_bounds__(256) void ln_kernel(const float* __restrict__ x,
                                                 const float* __restrict__ w,
                                                 const float* __restrict__ b,
                                                 __half* __restrict__ out)
{
    int row = blockIdx.x;
    const float* xr = x + (size_t)row * DIMC;
    float s = 0.f, s2 = 0.f;
    float vals[3];
    #pragma unroll
    for (int t = 0; t < 3; t++) {
        float v = xr[threadIdx.x + 256 * t];
        vals[t] = v; s += v; s2 += v * v;
    }
    __shared__ float shs[8], shs2[8];
    #pragma unroll
    for (int o = 16; o > 0; o >>= 1) {
        s  += __shfl_down_sync(0xffffffffu, s,  o);
        s2 += __shfl_down_sync(0xffffffffu, s2, o);
    }
    if ((threadIdx.x & 31) == 0) { shs[threadIdx.x >> 5] = s; shs2[threadIdx.x >> 5] = s2; }
    __syncthreads();
    __shared__ float sh_mean, sh_rstd;
    if (threadIdx.x == 0) {
        float ts = 0.f, ts2 = 0.f;
        #pragma unroll
        for (int i = 0; i < 8; i++) { ts += shs[i]; ts2 += shs2[i]; }
        float mean = ts / DIMC;
        float var  = ts2 / DIMC - mean * mean;
        sh_mean = mean;
        sh_rstd = rsqrtf(var + EPSLN);
    }
    __syncthreads();
    float mean = sh_mean, rstd = sh_rstd;
    __half* orow = out + (size_t)row * DIMC;
    #pragma unroll
    for (int t = 0; t < 3; t++) {
        int i = threadIdx.x + 256 * t;
        orow[i] = __float2half_rn((vals[t] - mean) * rstd * w[i] + b[i]);
    }
}

// ---------------- conv1d (temporal calibration), warp per output ----------------
__global__ __launch_bounds__(256) void conv_kernel(const float* __restrict__ wq,
                                                   const float* __restrict__ bq,
                                                   const float* __restrict__ wk,
                                                   const float* __restrict__ bk)
{
    int gw   = blockIdx.x * 8 + (threadIdx.x >> 5);
    int lane = threadIdx.x & 31;
    int which = gw / (BATCH * DIMC);
    int rem   = gw % (BATCH * DIMC);
    int bt = rem / DIMC;
    int co = rem % DIMC;
    int bv = bt >> 2, t = bt & 3;
    const float* w  = which ? wk : wq;
    const float* bb = which ? bk : bq;
    float s = 0.f;
    const __half* h0 = (t > 0) ? (g_h + (size_t)(bv * 4 + t - 1) * NTOK * DIMC) : nullptr;
    const __half* h1 = g_h + (size_t)(bv * 4 + t) * NTOK * DIMC;
    const __half* h2 = (t < 3) ? (g_h + (size_t)(bv * 4 + t + 1) * NTOK * DIMC) : nullptr;
    for (int ci = lane; ci < DIMC; ci += 32) {
        const float* wp = w + ((size_t)co * DIMC + ci) * 3;
        float w0 = wp[0], w1 = wp[1], w2 = wp[2];
        if (h0) s += w0 * __half2float(h0[ci]);
        s += w1 * __half2float(h1[ci]);
        if (h2) s += w2 * __half2float(h2[ci]);
    }
    #pragma unroll
    for (int o = 16; o > 0; o >>= 1) s += __shfl_down_sync(0xffffffffu, s, o);
    if (lane == 0) {
        float* dst = which ? g_ck : g_cq;
        dst[bt * DIMC + co] = s + bb[co];
    }
}

// ---------------- launch ----------------
extern "C" void kernel_launch(void* const* d_in, const int* in_sizes, int n_in,
                              void* d_out, int out_size)
{
    const float* x      = (const float*)d_in[0];
    const float* ln1_w  = (const float*)d_in[1];
    const float* ln1_b  = (const float*)d_in[2];
    const float* qkv_w  = (const float*)d_in[3];
    const float* qkv_b  = (const float*)d_in[4];
    const float* convq_w= (const float*)d_in[5];
    const float* convq_b= (const float*)d_in[6];
    const float* convk_w= (const float*)d_in[7];
    const float* convk_b= (const float*)d_in[8];
    const float* proj_w = (const float*)d_in[9];
    const float* proj_b = (const float*)d_in[10];
    const float* ln2_w  = (const float*)d_in[11];
    const float* ln2_b  = (const float*)d_in[12];
    const float* ff1_w  = (const float*)d_in[13];
    const float* ff1_b  = (const float*)d_in[14];
    const float* ff2_w  = (const float*)d_in[15];
    const float* ff2_b  = (const float*)d_in[16];
    float* out = (float*)d_out;

    __half* p_h;  cudaGetSymbolAddress((void**)&p_h,  g_h);
    __half* p_o;  cudaGetSymbolAddress((void**)&p_o,  g_o);
    float*  p_x1; cudaGetSymbolAddress((void**)&p_x1, g_x1);
    __half* p_ff; cudaGetSymbolAddress((void**)&p_ff, g_ff);
    __half* p_w;  cudaGetSymbolAddress((void**)&p_w,  g_wts);

    cudaFuncSetAttribute(tc_gemm<0>, cudaFuncAttributeMaxDynamicSharedMemorySize, TC_SMEM);
    cudaFuncSetAttribute(tc_gemm<1>, cudaFuncAttributeMaxDynamicSharedMemorySize, TC_SMEM);
    cudaFuncSetAttribute(tc_gemm<2>, cudaFuncAttributeMaxDynamicSharedMemorySize, TC_SMEM);
    cudaFuncSetAttribute(tc_gemm<3>, cudaFuncAttributeMaxDynamicSharedMemorySize, TC_SMEM);
    cudaFuncSetAttribute(attn_kernel, cudaFuncAttributeMaxDynamicSharedMemorySize, ATT_SMEM);

    const int MT = (MROWS + TBM - 1) / TBM;   // 50

    // 0. pre-convert all weights to fp16 (single launch)
    round_all_kernel<<<(N4_TOT + 255) / 256, 256>>>(qkv_w, proj_w, ff1_w, ff2_w, p_w);
    // 1. LN1 -> half g_h
    ln_kernel<<<MROWS, 256>>>(x, ln1_w, ln1_b, p_h);
    // 2. temporal conv on per-frame CLS tokens
    conv_kernel<<<(2 * BATCH * DIMC) / 8, 256>>>(convq_w, convq_b, convk_w, convk_b);
    // 3. QKV GEMM + scatter (+cq/ck) -> half q/k/v
    tc_gemm<0><<<dim3(3 * DIMC / TBN, MT), NTHR, TC_SMEM>>>(
        p_h, p_w + W_QKV_OFF, qkv_b, nullptr, nullptr, nullptr, MROWS, DIMC);
    // 4. fused fp16 attention (1 CTA per head) -> half g_o
    attn_kernel<<<BATCH * HEADS, 32 * ATTW, ATT_SMEM>>>();
    // 5. proj + residual -> fp32 g_x1
    tc_gemm<1><<<dim3(DIMC / TBN, MT), NTHR, TC_SMEM>>>(
        p_o, p_w + W_PROJ_OFF, proj_b, x, p_x1, nullptr, MROWS, DIMC);
    // 6. LN2 -> half g_h
    ln_kernel<<<MROWS, 256>>>(p_x1, ln2_w, ln2_b, p_h);
    // 7. FF1 + fast GELU -> half g_ff
    tc_gemm<2><<<dim3(FDIM / TBN, MT), NTHR, TC_SMEM>>>(
        p_h, p_w + W_FF1_OFF, ff1_b, nullptr, nullptr, p_ff, MROWS, DIMC);
    // 8. FF2 + residual -> fp32 out
    tc_gemm<3><<<dim3(DIMC / TBN, MT), NTHR, TC_SMEM>>>(
        p_ff, p_w + W_FF2_OFF, ff2_b, p_x1, out, nullptr, MROWS, FDIM);
}

// round 13
// speedup vs baseline: 1.1802x; 1.1802x over previous
#include <cuda_runtime.h>
#include <cuda_fp16.h>
#include <math.h>
#include <stdint.h>

// ---------------- problem constants ----------------
#define BATCH   64
#define NTOK    197
#define DIMC    768
#define HEADS   12
#define DHEAD   64
#define MROWS   (BATCH * NTOK)          // 12608
#define FDIM    (DIMC * 4)              // 3072
#define EPSLN   1e-6f

#define W_QKV_OFF  0
#define W_PROJ_OFF (3 * DIMC * DIMC)
#define W_FF1_OFF  (W_PROJ_OFF + DIMC * DIMC)
#define W_FF2_OFF  (W_FF1_OFF + FDIM * DIMC)
#define W_TOTAL    (W_FF2_OFF + DIMC * FDIM)

// ---------------- scratch (device globals, no allocation) ----------------
__device__ __half g_h  [MROWS * DIMC];                 // LN out (fp16)
__device__ __half g_q  [BATCH * HEADS * NTOK * DHEAD]; // q + cq (fp16)
__device__ __half g_k  [BATCH * HEADS * NTOK * DHEAD];
__device__ __half g_v  [BATCH * HEADS * NTOK * DHEAD];
__device__ float  g_cq [BATCH * DIMC];
__device__ float  g_ck [BATCH * DIMC];
__device__ __half g_o  [MROWS * DIMC];                 // attn out (fp16)
__device__ float  g_x1 [MROWS * DIMC];                 // x + attn branch (fp32)
__device__ __half g_ff [MROWS * FDIM];                 // gelu(ff1) (fp16)
__device__ __half g_wts[W_TOTAL];                      // fp16 weights

// ================= helpers =================
__device__ __forceinline__ void mma_f16(float* d, const uint32_t* a, const uint32_t* b) {
    asm volatile(
        "mma.sync.aligned.m16n8k16.row.col.f32.f16.f16.f32 "
        "{%0,%1,%2,%3}, {%4,%5,%6,%7}, {%8,%9}, {%0,%1,%2,%3};"
        : "+f"(d[0]), "+f"(d[1]), "+f"(d[2]), "+f"(d[3])
        : "r"(a[0]), "r"(a[1]), "r"(a[2]), "r"(a[3]), "r"(b[0]), "r"(b[1]));
}
__device__ __forceinline__ void ldsm_x4(uint32_t* r, uint32_t addr) {
    asm volatile("ldmatrix.sync.aligned.m8n8.x4.shared.b16 {%0,%1,%2,%3}, [%4];"
                 : "=r"(r[0]), "=r"(r[1]), "=r"(r[2]), "=r"(r[3]) : "r"(addr));
}
__device__ __forceinline__ uint32_t smem_u32(const void* p) {
    uint32_t a;
    asm("{ .reg .u64 t; cvta.to.shared.u64 t, %1; cvt.u32.u64 %0, t; }" : "=r"(a) : "l"(p));
    return a;
}
__device__ __forceinline__ void cpa16(uint32_t dst, const void* src, int sz) {
    asm volatile("cp.async.cg.shared.global [%0], [%1], 16, %2;" :: "r"(dst), "l"(src), "r"(sz));
}
#define CP_COMMIT asm volatile("cp.async.commit_group;" ::: "memory")
#define CP_WAIT0  asm volatile("cp.async.wait_group 0;" ::: "memory")

// fast exact-GELU via Abramowitz-Stegun 7.1.26 erf (|abs err| <= 1.5e-7)
__device__ __forceinline__ float fast_gelu(float v) {
    float z = fabsf(v) * 0.70710678118654752f;
    float t = __fdividef(1.0f, fmaf(0.3275911f, z, 1.0f));
    float poly = t * fmaf(t, fmaf(t, fmaf(t, fmaf(t, 1.061405429f, -1.453152027f),
                         1.421413741f), -0.284496736f), 0.254829592f);
    float er = 1.0f - poly * __expf(-z * z);
    er = copysignf(er, v);
    return 0.5f * v * (1.0f + er);
}

// ================= merged weight pre-conversion fp32 -> fp16 =================
#define N4_QKV  (3 * DIMC * DIMC / 4)
#define N4_PROJ (DIMC * DIMC / 4)
#define N4_FF1  (FDIM * DIMC / 4)
#define N4_TOT  (W_TOTAL / 4)
__global__ __launch_bounds__(256) void round_all_kernel(const float* __restrict__ qkv,
                                                        const float* __restrict__ proj,
                                                        const float* __restrict__ ff1,
                                                        const float* __restrict__ ff2,
                                                        __half* __restrict__ dst)
{
    int i = blockIdx.x * 256 + threadIdx.x;
    if (i >= N4_TOT) return;
    const float* src;
    int j = i;
    if (j < N4_QKV) src = qkv;
    else if ((j -= N4_QKV) < N4_PROJ) src = proj;
    else if ((j -= N4_PROJ) < N4_FF1) src = ff1;
    else { j -= N4_FF1; src = ff2; }
    float4 v = ((const float4*)src)[j];
    ((__half2*)dst)[2 * i]     = __floats2half2_rn(v.x, v.y);
    ((__half2*)dst)[2 * i + 1] = __floats2half2_rn(v.z, v.w);
}

// ========= fp16 mma GEMM, 256x128 tile, 1024 thr (32 warps, 32x32 warp tile), 2-stage =========
// MODE 0: QKV scatter (+cq/ck) -> half q/k/v, MODE 1: proj + resid -> fp32,
// MODE 2: ff1 + gelu -> half g_ff, MODE 3: ff2 + resid -> fp32 out
#define TBM 256
#define TBN 128
#define TBK 64
#define NTHR 1024
#define HPAD 72
#define ABUF_A (TBM * HPAD * 2)          // 36864 B
#define ABUF_B (TBN * HPAD * 2)          // 18432 B
#define STG_BYTES (ABUF_A + ABUF_B)      // 55296 B
#define TC_SMEM (2 * STG_BYTES)          // 110592 B -> 1 CTA/SM, 32 warps

template<int MODE>
__global__ __launch_bounds__(NTHR, 1)
void tc_gemm(const __half* __restrict__ A, const __half* __restrict__ W,
             const float* __restrict__ bias, const float* __restrict__ resid,
             float* __restrict__ out, __half* __restrict__ hout, int M, int K)
{
    extern __shared__ char smem[];
    const uint32_t sb32 = smem_u32(smem);
    const int tid = threadIdx.x;
    const int wid = tid >> 5, lane = tid & 31;
    const int qr = lane >> 2, qc = lane & 3;
    const int wm = wid >> 2, wn = wid & 3;          // 8 x 4 warp grid, 32x32 warp tiles
    const int m0 = blockIdx.y * TBM, n0 = blockIdx.x * TBN;

    // A staging: 1024 threads cover 256 rows x 64 halves (quarter-row = 16 halves each)
    const int sr  = tid >> 2;            // 0..255
    const int sub = tid & 3;             // 16 halves = 2x16B
    const int aok = ((m0 + sr) < M) ? 16 : 0;
    const __half* ap = A + (size_t)(m0 + sr) * K + sub * 16;
    const uint32_t da = sb32 + (sr * HPAD + sub * 16) * 2;
    // B staging: 1024 threads cover 128 rows x 64 halves (eighth-row = 8 halves each)
    const int srb  = tid >> 3;           // 0..127
    const int subb = tid & 7;            // 8 halves = 1x16B
    const __half* bp = W + (size_t)(n0 + srb) * K + subb * 8;
    const uint32_t db = sb32 + ABUF_A + (srb * HPAD + subb * 8) * 2;

    const int a_row  = (lane & 15);
    const int a_koff = (lane >> 4) << 3;
    const int b_row  = (lane & 7) + ((lane >> 4) << 3);
    const int b_koff = ((lane >> 3) & 1) << 3;
    uint32_t aoff[2], boff[2];
    #pragma unroll
    for (int mt = 0; mt < 2; mt++)
        aoff[mt] = ((wm * 32 + mt * 16 + a_row) * HPAD + a_koff) * 2;
    #pragma unroll
    for (int np = 0; np < 2; np++)
        boff[np] = ABUF_A + ((wn * 32 + np * 16 + b_row) * HPAD + b_koff) * 2;

    float acc[2][4][4];
    #pragma unroll
    for (int i = 0; i < 2; i++)
        #pragma unroll
        for (int j = 0; j < 4; j++)
            #pragma unroll
            for (int t = 0; t < 4; t++) acc[i][j][t] = 0.f;

    const int NC = K / TBK;

    // prologue: stage 0
    #pragma unroll
    for (int q = 0; q < 2; q++) cpa16(da + q * 16, ap + q * 8, aok);
    cpa16(db, bp, 16);
    CP_COMMIT;

    for (int c = 0; c < NC; c++) {
        CP_WAIT0;
        __syncthreads();        // all warps done with chunk c-1 -> buf (c+1)&1 free
        if (c + 1 < NC) {
            const uint32_t so = ((c + 1) & 1) * STG_BYTES;
            const int kk = (c + 1) * TBK;
            #pragma unroll
            for (int q = 0; q < 2; q++) cpa16(da + so + q * 16, ap + kk + q * 8, aok);
            cpa16(db + so, bp + kk, 16);
            CP_COMMIT;
        }

        const uint32_t sbase = sb32 + (c & 1) * STG_BYTES;
        #pragma unroll
        for (int ks = 0; ks < 4; ks++) {
            const uint32_t kb = sbase + (ks * 16) * 2;
            uint32_t afr[2][4], bfr[4][2];
            #pragma unroll
            for (int mt = 0; mt < 2; mt++)
                ldsm_x4(afr[mt], kb + aoff[mt]);
            #pragma unroll
            for (int np = 0; np < 2; np++) {
                uint32_t r[4];
                ldsm_x4(r, kb + boff[np]);
                bfr[2 * np][0] = r[0]; bfr[2 * np][1] = r[1];
                bfr[2 * np + 1][0] = r[2]; bfr[2 * np + 1][1] = r[3];
            }
            #pragma unroll
            for (int mt = 0; mt < 2; mt++)
                #pragma unroll
                for (int nt = 0; nt < 4; nt++)
                    mma_f16(acc[mt][nt], afr[mt], bfr[nt]);
        }
    }

    // ---- epilogue: fused stores ----
    #pragma unroll
    for (int mt = 0; mt < 2; mt++) {
        int mA = m0 + wm * 32 + mt * 16 + qr;
        #pragma unroll
        for (int nt = 0; nt < 4; nt++) {
            int col = n0 + wn * 32 + nt * 8 + 2 * qc;
            float2 b2 = *(const float2*)&bias[col];
            #pragma unroll
            for (int half = 0; half < 2; half++) {
                int m = mA + half * 8;
                if (m >= M) continue;
                float v0 = acc[mt][nt][half * 2 + 0] + b2.x;
                float v1 = acc[mt][nt][half * 2 + 1] + b2.y;
                if (MODE == 0) {
                    int which = col / DIMC;
                    int r = col - which * DIMC;
                    int bI = m / NTOK, nI = m - bI * NTOK;
                    int h = r >> 6, d = r & 63;
                    __half* dst;
                    if (which == 0) {
                        float2 c2 = *(const float2*)&g_cq[bI * DIMC + r];
                        v0 += c2.x; v1 += c2.y; dst = g_q;
                    } else if (which == 1) {
                        float2 c2 = *(const float2*)&g_ck[bI * DIMC + r];
                        v0 += c2.x; v1 += c2.y; dst = g_k;
                    } else dst = g_v;
                    *(__half2*)&dst[((size_t)(bI * HEADS + h) * NTOK + nI) * DHEAD + d] =
                        __floats2half2_rn(v0, v1);
                } else if (MODE == 1 || MODE == 3) {
                    size_t ix = (size_t)m * DIMC + col;
                    float2 r2 = *(const float2*)&resid[ix];
                    *(float2*)&out[ix] = make_float2(v0 + r2.x, v1 + r2.y);
                } else { // MODE 2: fast gelu -> half g_ff
                    v0 = fast_gelu(v0);
                    v1 = fast_gelu(v1);
                    *(__half2*)&hout[(size_t)m * FDIM + col] = __floats2half2_rn(v0, v1);
                }
            }
        }
    }
}

// ================= fused attention: 1 CTA per (b,h), 4 q-blocks, fp16 mma =================
#define ATTW 16
#define QH_STR 72
#define KH_STR 72
#define VT_STR 216
#define PH_STR 216
#define AS_STR 212
#define SM_Q  0
#define SM_K  9216
#define SM_VT 39168
#define SM_P  66816
#define SM_S  94464
#define ATT_SMEM 148736

__global__ __launch_bounds__(32 * ATTW, 1) void attn_kernel()
{
    extern __shared__ char sm[];
    const uint32_t sb = smem_u32(sm);
    __half* Qs = (__half*)(sm + SM_Q);
    __half* Ks = (__half*)(sm + SM_K);
    __half* Vt = (__half*)(sm + SM_VT);
    __half* Ps = (__half*)(sm + SM_P);
    float*  Ss = (float*)(sm + SM_S);

    const int tid = threadIdx.x;
    const int wid = tid >> 5, lane = tid & 31;
    const int qr = lane >> 2, qc = lane & 3;
    const int bh = blockIdx.x;
    const int b = bh / HEADS, h = bh - (bh / HEADS) * HEADS;

    const __half* Qg = g_q + (size_t)bh * NTOK * DHEAD;
    const __half* Kg = g_k + (size_t)bh * NTOK * DHEAD;
    const __half* Vg = g_v + (size_t)bh * NTOK * DHEAD;

    // ---- load K (208x64, zero-padded) and V transposed (once per head) ----
    for (int idx = tid; idx < 208 * 8; idx += 32 * ATTW) {
        int r = idx >> 3, c8 = (idx & 7) * 8;
        uint4 v = make_uint4(0u, 0u, 0u, 0u);
        if (r < NTOK) v = *(const uint4*)&Kg[r * DHEAD + c8];
        *(uint4*)&Ks[r * KH_STR + c8] = v;
    }
    for (int idx = tid; idx < 208 * 8; idx += 32 * ATTW) {
        int key = idx >> 3, g = idx & 7, d8 = g * 8;
        __half vals[8];
        uint4 v = make_uint4(0u, 0u, 0u, 0u);
        if (key < NTOK) v = *(const uint4*)&Vg[key * DHEAD + d8];
        *(uint4*)vals = v;
        #pragma unroll
        for (int j = 0; j < 8; j++) {
            int jj = (j + g) & 7;
            Vt[(d8 + jj) * VT_STR + key] = vals[jj];
        }
    }

    const int a_row  = (lane & 15);
    const int a_koff = (lane >> 4) << 3;
    const int b_row  = (lane & 7) + ((lane >> 4) << 3);
    const int b_koff = ((lane >> 3) & 1) << 3;

    for (int blk = 0; blk < 4; blk++) {
        const int m0 = blk * 64;
        // ---- load Q block (64x64) ----
        {
            int r = tid >> 3, c8 = (tid & 7) * 8;
            int gr = m0 + r;
            uint4 v = make_uint4(0u, 0u, 0u, 0u);
            if (gr < NTOK) v = *(const uint4*)&Qg[gr * DHEAD + c8];
            *(uint4*)&Qs[r * QH_STR + c8] = v;
        }
        __syncthreads();    // K/V (first iter) and Q visible; prev PV done

        // ---- S = Q K^T * 0.125 ----
        for (int t = wid; t < 52; t += ATTW) {
            int mt = t & 3, kp = t >> 2;
            float acc0[4] = {0.f, 0.f, 0.f, 0.f};
            float acc1[4] = {0.f, 0.f, 0.f, 0.f};
            #pragma unroll
            for (int ks = 0; ks < 4; ks++) {
                uint32_t a[4], r[4];
                ldsm_x4(a, sb + SM_Q + (uint32_t)((mt * 16 + a_row) * QH_STR + ks * 16 + a_koff) * 2);
                ldsm_x4(r, sb + SM_K + (uint32_t)((kp * 16 + b_row) * KH_STR + ks * 16 + b_koff) * 2);
                uint32_t b0[2] = {r[0], r[1]}, b1[2] = {r[2], r[3]};
                mma_f16(acc0, a, b0);
                mma_f16(acc1, a, b1);
            }
            int r0 = mt * 16 + qr;
            int c0 = kp * 16 + 2 * qc;
            Ss[r0 * AS_STR + c0]            = acc0[0] * 0.125f;
            Ss[r0 * AS_STR + c0 + 1]        = acc0[1] * 0.125f;
            Ss[(r0 + 8) * AS_STR + c0]      = acc0[2] * 0.125f;
            Ss[(r0 + 8) * AS_STR + c0 + 1]  = acc0[3] * 0.125f;
            Ss[r0 * AS_STR + c0 + 8]        = acc1[0] * 0.125f;
            Ss[r0 * AS_STR + c0 + 9]        = acc1[1] * 0.125f;
            Ss[(r0 + 8) * AS_STR + c0 + 8]  = acc1[2] * 0.125f;
            Ss[(r0 + 8) * AS_STR + c0 + 9]  = acc1[3] * 0.125f;
        }
        __syncthreads();

        // ---- row softmax -> P (half) ----
        #pragma unroll
        for (int rr = 0; rr < 4; rr++) {
            int r = wid * 4 + rr;
            float vbuf[7];
            float mx = -1e30f;
            #pragma unroll
            for (int t = 0; t < 7; t++) {
                int col = lane + 32 * t;
                float v = (col < NTOK) ? Ss[r * AS_STR + col] : -1e30f;
                vbuf[t] = v;
                mx = fmaxf(mx, v);
            }
            #pragma unroll
            for (int o = 16; o > 0; o >>= 1)
                mx = fmaxf(mx, __shfl_xor_sync(0xffffffffu, mx, o));
            float sum = 0.f;
            #pragma unroll
            for (int t = 0; t < 7; t++) {
                int col = lane + 32 * t;
                float e = (col < NTOK) ? expf(vbuf[t] - mx) : 0.f;
                vbuf[t] = e;
                sum += e;
            }
            #pragma unroll
            for (int o = 16; o > 0; o >>= 1)
                sum += __shfl_xor_sync(0xffffffffu, sum, o);
            float inv = 1.0f / sum;
            #pragma unroll
            for (int t = 0; t < 7; t++) {
                int col = lane + 32 * t;
                if (col < 208)
                    Ps[r * PH_STR + col] = __float2half_rn((col < NTOK) ? vbuf[t] * inv : 0.f);
            }
        }
        __syncthreads();

        // ---- O = P V : one 16x16 output tile per warp ----
        {
            const int mt = wid & 3, np = wid >> 2;
            float acc0[4] = {0.f, 0.f, 0.f, 0.f};
            float acc1[4] = {0.f, 0.f, 0.f, 0.f};
            #pragma unroll
            for (int ks = 0; ks < 13; ks++) {
                uint32_t a[4], r[4];
                ldsm_x4(a, sb + SM_P  + (uint32_t)((mt * 16 + a_row) * PH_STR + ks * 16 + a_koff) * 2);
                ldsm_x4(r, sb + SM_VT + (uint32_t)((np * 16 + b_row) * VT_STR + ks * 16 + b_koff) * 2);
                uint32_t b0[2] = {r[0], r[1]}, b1[2] = {r[2], r[3]};
                mma_f16(acc0, a, b0);
                mma_f16(acc1, a, b1);
            }
            #pragma unroll
            for (int hf = 0; hf < 2; hf++) {
                int gr = m0 + mt * 16 + qr + hf * 8;
                if (gr < NTOK) {
                    size_t base = (size_t)(b * NTOK + gr) * DIMC + h * DHEAD + np * 16 + 2 * qc;
                    *(__half2*)&g_o[base]     = __floats2half2_rn(acc0[hf * 2], acc0[hf * 2 + 1]);
                    *(__half2*)&g_o[base + 8] = __floats2half2_rn(acc1[hf * 2], acc1[hf * 2 + 1]);
                }
            }
        }
    }
}

// ---------------- layernorm (fp16 output) ----------------
__global__ __launch_bounds__(256) void ln_kernel(const float* __restrict__ x,
                                                 const float* __restrict__ w,
                                                 const float* __restrict__ b,
                                                 __half* __restrict__ out)
{
    int row = blockIdx.x;
    const float* xr = x + (size_t)row * DIMC;
    float s = 0.f, s2 = 0.f;
    float vals[3];
    #pragma unroll
    for (int t = 0; t < 3; t++) {
        float v = xr[threadIdx.x + 256 * t];
        vals[t] = v; s += v; s2 += v * v;
    }
    __shared__ float shs[8], shs2[8];
    #pragma unroll
    for (int o = 16; o > 0; o >>= 1) {
        s  += __shfl_down_sync(0xffffffffu, s,  o);
        s2 += __shfl_down_sync(0xffffffffu, s2, o);
    }
    if ((threadIdx.x & 31) == 0) { shs[threadIdx.x >> 5] = s; shs2[threadIdx.x >> 5] = s2; }
    __syncthreads();
    __shared__ float sh_mean, sh_rstd;
    if (threadIdx.x == 0) {
        float ts = 0.f, ts2 = 0.f;
        #pragma unroll
        for (int i = 0; i < 8; i++) { ts += shs[i]; ts2 += shs2[i]; }
        float mean = ts / DIMC;
        float var  = ts2 / DIMC - mean * mean;
        sh_mean = mean;
        sh_rstd = rsqrtf(var + EPSLN);
    }
    __syncthreads();
    float mean = sh_mean, rstd = sh_rstd;
    __half* orow = out + (size_t)row * DIMC;
    #pragma unroll
    for (int t = 0; t < 3; t++) {
        int i = threadIdx.x + 256 * t;
        orow[i] = __float2half_rn((vals[t] - mean) * rstd * w[i] + b[i]);
    }
}

// ---------------- conv1d (temporal calibration), warp per output ----------------
__global__ __launch_bounds__(256) void conv_kernel(const float* __restrict__ wq,
                                                   const float* __restrict__ bq,
                                                   const float* __restrict__ wk,
                                                   const float* __restrict__ bk)
{
    int gw   = blockIdx.x * 8 + (threadIdx.x >> 5);
    int lane = threadIdx.x & 31;
    int which = gw / (BATCH * DIMC);
    int rem   = gw % (BATCH * DIMC);
    int bt = rem / DIMC;
    int co = rem % DIMC;
    int bv = bt >> 2, t = bt & 3;
    const float* w  = which ? wk : wq;
    const float* bb = which ? bk : bq;
    float s = 0.f;
    const __half* h0 = (t > 0) ? (g_h + (size_t)(bv * 4 + t - 1) * NTOK * DIMC) : nullptr;
    const __half* h1 = g_h + (size_t)(bv * 4 + t) * NTOK * DIMC;
    const __half* h2 = (t < 3) ? (g_h + (size_t)(bv * 4 + t + 1) * NTOK * DIMC) : nullptr;
    for (int ci = lane; ci < DIMC; ci += 32) {
        const float* wp = w + ((size_t)co * DIMC + ci) * 3;
        float w0 = wp[0], w1 = wp[1], w2 = wp[2];
        if (h0) s += w0 * __half2float(h0[ci]);
        s += w1 * __half2float(h1[ci]);
        if (h2) s += w2 * __half2float(h2[ci]);
    }
    #pragma unroll
    for (int o = 16; o > 0; o >>= 1) s += __shfl_down_sync(0xffffffffu, s, o);
    if (lane == 0) {
        float* dst = which ? g_ck : g_cq;
        dst[bt * DIMC + co] = s + bb[co];
    }
}

// ---------------- launch ----------------
extern "C" void kernel_launch(void* const* d_in, const int* in_sizes, int n_in,
                              void* d_out, int out_size)
{
    const float* x      = (const float*)d_in[0];
    const float* ln1_w  = (const float*)d_in[1];
    const float* ln1_b  = (const float*)d_in[2];
    const float* qkv_w  = (const float*)d_in[3];
    const float* qkv_b  = (const float*)d_in[4];
    const float* convq_w= (const float*)d_in[5];
    const float* convq_b= (const float*)d_in[6];
    const float* convk_w= (const float*)d_in[7];
    const float* convk_b= (const float*)d_in[8];
    const float* proj_w = (const float*)d_in[9];
    const float* proj_b = (const float*)d_in[10];
    const float* ln2_w  = (const float*)d_in[11];
    const float* ln2_b  = (const float*)d_in[12];
    const float* ff1_w  = (const float*)d_in[13];
    const float* ff1_b  = (const float*)d_in[14];
    const float* ff2_w  = (const float*)d_in[15];
    const float* ff2_b  = (const float*)d_in[16];
    float* out = (float*)d_out;

    __half* p_h;  cudaGetSymbolAddress((void**)&p_h,  g_h);
    __half* p_o;  cudaGetSymbolAddress((void**)&p_o,  g_o);
    float*  p_x1; cudaGetSymbolAddress((void**)&p_x1, g_x1);
    __half* p_ff; cudaGetSymbolAddress((void**)&p_ff, g_ff);
    __half* p_w;  cudaGetSymbolAddress((void**)&p_w,  g_wts);

    cudaFuncSetAttribute(tc_gemm<0>, cudaFuncAttributeMaxDynamicSharedMemorySize, TC_SMEM);
    cudaFuncSetAttribute(tc_gemm<1>, cudaFuncAttributeMaxDynamicSharedMemorySize, TC_SMEM);
    cudaFuncSetAttribute(tc_gemm<2>, cudaFuncAttributeMaxDynamicSharedMemorySize, TC_SMEM);
    cudaFuncSetAttribute(tc_gemm<3>, cudaFuncAttributeMaxDynamicSharedMemorySize, TC_SMEM);
    cudaFuncSetAttribute(attn_kernel, cudaFuncAttributeMaxDynamicSharedMemorySize, ATT_SMEM);

    const int MT = (MROWS + TBM - 1) / TBM;   // 50

    // 0. pre-convert all weights to fp16 (single launch)
    round_all_kernel<<<(N4_TOT + 255) / 256, 256>>>(qkv_w, proj_w, ff1_w, ff2_w, p_w);
    // 1. LN1 -> half g_h
    ln_kernel<<<MROWS, 256>>>(x, ln1_w, ln1_b, p_h);
    // 2. temporal conv on per-frame CLS tokens
    conv_kernel<<<(2 * BATCH * DIMC) / 8, 256>>>(convq_w, convq_b, convk_w, convk_b);
    // 3. QKV GEMM + scatter (+cq/ck) -> half q/k/v
    tc_gemm<0><<<dim3(3 * DIMC / TBN, MT), NTHR, TC_SMEM>>>(
        p_h, p_w + W_QKV_OFF, qkv_b, nullptr, nullptr, nullptr, MROWS, DIMC);
    // 4. fused fp16 attention (1 CTA per head) -> half g_o
    attn_kernel<<<BATCH * HEADS, 32 * ATTW, ATT_SMEM>>>();
    // 5. proj + residual -> fp32 g_x1
    tc_gemm<1><<<dim3(DIMC / TBN, MT), NTHR, TC_SMEM>>>(
        p_o, p_w + W_PROJ_OFF, proj_b, x, p_x1, nullptr, MROWS, DIMC);
    // 6. LN2 -> half g_h
    ln_kernel<<<MROWS, 256>>>(p_x1, ln2_w, ln2_b, p_h);
    // 7. FF1 + fast GELU -> half g_ff
    tc_gemm<2><<<dim3(FDIM / TBN, MT), NTHR, TC_SMEM>>>(
        p_h, p_w + W_FF1_OFF, ff1_b, nullptr, nullptr, p_ff, MROWS, DIMC);
    // 8. FF2 + residual -> fp32 out
    tc_gemm<3><<<dim3(DIMC / TBN, MT), NTHR, TC_SMEM>>>(
        p_ff, p_w + W_FF2_OFF, ff2_b, p_x1, out, nullptr, MROWS, FDIM);
}

// round 14
// speedup vs baseline: 1.2012x; 1.0178x over previous
#include <cuda_runtime.h>
#include <cuda_fp16.h>
#include <math.h>
#include <stdint.h>

// ---------------- problem constants ----------------
#define BATCH   64
#define NTOK    197
#define DIMC    768
#define HEADS   12
#define DHEAD   64
#define MROWS   (BATCH * NTOK)          // 12608
#define FDIM    (DIMC * 4)              // 3072
#define EPSLN   1e-6f

#define W_QKV_OFF  0
#define W_PROJ_OFF (3 * DIMC * DIMC)
#define W_FF1_OFF  (W_PROJ_OFF + DIMC * DIMC)
#define W_FF2_OFF  (W_FF1_OFF + FDIM * DIMC)
#define W_TOTAL    (W_FF2_OFF + DIMC * FDIM)

// ---------------- scratch (device globals, no allocation) ----------------
__device__ __half g_h  [MROWS * DIMC];                 // LN out (fp16)
__device__ __half g_q  [BATCH * HEADS * NTOK * DHEAD]; // q + cq (fp16)
__device__ __half g_k  [BATCH * HEADS * NTOK * DHEAD];
__device__ __half g_v  [BATCH * HEADS * NTOK * DHEAD];
__device__ float  g_cq [BATCH * DIMC];
__device__ float  g_ck [BATCH * DIMC];
__device__ __half g_o  [MROWS * DIMC];                 // attn out (fp16)
__device__ float  g_x1 [MROWS * DIMC];                 // x + attn branch (fp32)
__device__ __half g_ff [MROWS * FDIM];                 // gelu(ff1) (fp16)
__device__ __half g_wts[W_TOTAL];                      // fp16 weights

// ================= helpers =================
__device__ __forceinline__ void mma_f16(float* d, const uint32_t* a, const uint32_t* b) {
    asm volatile(
        "mma.sync.aligned.m16n8k16.row.col.f32.f16.f16.f32 "
        "{%0,%1,%2,%3}, {%4,%5,%6,%7}, {%8,%9}, {%0,%1,%2,%3};"
        : "+f"(d[0]), "+f"(d[1]), "+f"(d[2]), "+f"(d[3])
        : "r"(a[0]), "r"(a[1]), "r"(a[2]), "r"(a[3]), "r"(b[0]), "r"(b[1]));
}
__device__ __forceinline__ void ldsm_x4(uint32_t* r, uint32_t addr) {
    asm volatile("ldmatrix.sync.aligned.m8n8.x4.shared.b16 {%0,%1,%2,%3}, [%4];"
                 : "=r"(r[0]), "=r"(r[1]), "=r"(r[2]), "=r"(r[3]) : "r"(addr));
}
__device__ __forceinline__ uint32_t smem_u32(const void* p) {
    uint32_t a;
    asm("{ .reg .u64 t; cvta.to.shared.u64 t, %1; cvt.u32.u64 %0, t; }" : "=r"(a) : "l"(p));
    return a;
}
__device__ __forceinline__ void cpa16(uint32_t dst, const void* src, int sz) {
    asm volatile("cp.async.cg.shared.global [%0], [%1], 16, %2;" :: "r"(dst), "l"(src), "r"(sz));
}
#define CP_COMMIT asm volatile("cp.async.commit_group;" ::: "memory")
#define CP_WAIT0  asm volatile("cp.async.wait_group 0;" ::: "memory")

// fast exact-GELU via Abramowitz-Stegun 7.1.26 erf (|abs err| <= 1.5e-7)
__device__ __forceinline__ float fast_gelu(float v) {
    float z = fabsf(v) * 0.70710678118654752f;
    float t = __fdividef(1.0f, fmaf(0.3275911f, z, 1.0f));
    float poly = t * fmaf(t, fmaf(t, fmaf(t, fmaf(t, 1.061405429f, -1.453152027f),
                         1.421413741f), -0.284496736f), 0.254829592f);
    float er = 1.0f - poly * __expf(-z * z);
    er = copysignf(er, v);
    return 0.5f * v * (1.0f + er);
}

// ================= merged weight pre-conversion fp32 -> fp16 =================
#define N4_QKV  (3 * DIMC * DIMC / 4)
#define N4_PROJ (DIMC * DIMC / 4)
#define N4_FF1  (FDIM * DIMC / 4)
#define N4_TOT  (W_TOTAL / 4)
__global__ __launch_bounds__(256) void round_all_kernel(const float* __restrict__ qkv,
                                                        const float* __restrict__ proj,
                                                        const float* __restrict__ ff1,
                                                        const float* __restrict__ ff2,
                                                        __half* __restrict__ dst)
{
    int i = blockIdx.x * 256 + threadIdx.x;
    if (i >= N4_TOT) return;
    const float* src;
    int j = i;
    if (j < N4_QKV) src = qkv;
    else if ((j -= N4_QKV) < N4_PROJ) src = proj;
    else if ((j -= N4_PROJ) < N4_FF1) src = ff1;
    else { j -= N4_FF1; src = ff2; }
    float4 v = ((const float4*)src)[j];
    ((__half2*)dst)[2 * i]     = __floats2half2_rn(v.x, v.y);
    ((__half2*)dst)[2 * i + 1] = __floats2half2_rn(v.z, v.w);
}

// ==== fp16 mma GEMM, 128x128 tile, 512 thr (16 warps, 32x32 warp tile), 2-stage, 2 CTAs/SM ====
// MODE 0: QKV scatter (+cq/ck) -> half q/k/v, MODE 1: proj + resid -> fp32,
// MODE 2: ff1 + gelu -> half g_ff, MODE 3: ff2 + resid -> fp32 out
#define TBM 128
#define TBN 128
#define TBK 64
#define NTHR 512
#define HPAD 72
#define ABUF_A (TBM * HPAD * 2)          // 18432 B
#define ABUF_B (TBN * HPAD * 2)          // 18432 B
#define STG_BYTES (ABUF_A + ABUF_B)      // 36864 B
#define TC_SMEM (2 * STG_BYTES)          // 73728 B -> 2 CTAs/SM, 32 warps/SM

template<int MODE>
__global__ __launch_bounds__(NTHR, 2)
void tc_gemm(const __half* __restrict__ A, const __half* __restrict__ W,
             const float* __restrict__ bias, const float* __restrict__ resid,
             float* __restrict__ out, __half* __restrict__ hout, int M, int K)
{
    extern __shared__ char smem[];
    const uint32_t sb32 = smem_u32(smem);
    const int tid = threadIdx.x;
    const int wid = tid >> 5, lane = tid & 31;
    const int qr = lane >> 2, qc = lane & 3;
    const int wm = wid >> 2, wn = wid & 3;          // 4 x 4 warp grid, 32x32 warp tiles
    const int m0 = blockIdx.y * TBM, n0 = blockIdx.x * TBN;

    // A staging: 512 threads cover 128 rows x 64 halves (quarter-row = 16 halves)
    const int sr  = tid >> 2;            // 0..127
    const int sub = tid & 3;             // 16 halves = 2x16B
    const int aok = ((m0 + sr) < M) ? 16 : 0;
    const __half* ap = A + (size_t)(m0 + sr) * K + sub * 16;
    const uint32_t da = sb32 + (sr * HPAD + sub * 16) * 2;
    // B staging: identical shape
    const __half* bp = W + (size_t)(n0 + sr) * K + sub * 16;
    const uint32_t db = sb32 + ABUF_A + (sr * HPAD + sub * 16) * 2;

    const int a_row  = (lane & 15);
    const int a_koff = (lane >> 4) << 3;
    const int b_row  = (lane & 7) + ((lane >> 4) << 3);
    const int b_koff = ((lane >> 3) & 1) << 3;
    uint32_t aoff[2], boff[2];
    #pragma unroll
    for (int mt = 0; mt < 2; mt++)
        aoff[mt] = ((wm * 32 + mt * 16 + a_row) * HPAD + a_koff) * 2;
    #pragma unroll
    for (int np = 0; np < 2; np++)
        boff[np] = ABUF_A + ((wn * 32 + np * 16 + b_row) * HPAD + b_koff) * 2;

    float acc[2][4][4];
    #pragma unroll
    for (int i = 0; i < 2; i++)
        #pragma unroll
        for (int j = 0; j < 4; j++)
            #pragma unroll
            for (int t = 0; t < 4; t++) acc[i][j][t] = 0.f;

    const int NC = K / TBK;

    // prologue: stage 0
    #pragma unroll
    for (int q = 0; q < 2; q++) {
        cpa16(da + q * 16, ap + q * 8, aok);
        cpa16(db + q * 16, bp + q * 8, 16);
    }
    CP_COMMIT;

    for (int c = 0; c < NC; c++) {
        CP_WAIT0;
        __syncthreads();        // all warps done with chunk c-1 -> buf (c+1)&1 free
        if (c + 1 < NC) {
            const uint32_t so = ((c + 1) & 1) * STG_BYTES;
            const int kk = (c + 1) * TBK;
            #pragma unroll
            for (int q = 0; q < 2; q++) {
                cpa16(da + so + q * 16, ap + kk + q * 8, aok);
                cpa16(db + so + q * 16, bp + kk + q * 8, 16);
            }
            CP_COMMIT;
        }

        const uint32_t sbase = sb32 + (c & 1) * STG_BYTES;
        #pragma unroll
        for (int ks = 0; ks < 4; ks++) {
            const uint32_t kb = sbase + (ks * 16) * 2;
            uint32_t afr[2][4], bfr[4][2];
            #pragma unroll
            for (int mt = 0; mt < 2; mt++)
                ldsm_x4(afr[mt], kb + aoff[mt]);
            #pragma unroll
            for (int np = 0; np < 2; np++) {
                uint32_t r[4];
                ldsm_x4(r, kb + boff[np]);
                bfr[2 * np][0] = r[0]; bfr[2 * np][1] = r[1];
                bfr[2 * np + 1][0] = r[2]; bfr[2 * np + 1][1] = r[3];
            }
            #pragma unroll
            for (int mt = 0; mt < 2; mt++)
                #pragma unroll
                for (int nt = 0; nt < 4; nt++)
                    mma_f16(acc[mt][nt], afr[mt], bfr[nt]);
        }
    }

    // ---- epilogue: fused stores ----
    #pragma unroll
    for (int mt = 0; mt < 2; mt++) {
        int mA = m0 + wm * 32 + mt * 16 + qr;
        #pragma unroll
        for (int nt = 0; nt < 4; nt++) {
            int col = n0 + wn * 32 + nt * 8 + 2 * qc;
            float2 b2 = *(const float2*)&bias[col];
            #pragma unroll
            for (int half = 0; half < 2; half++) {
                int m = mA + half * 8;
                if (m >= M) continue;
                float v0 = acc[mt][nt][half * 2 + 0] + b2.x;
                float v1 = acc[mt][nt][half * 2 + 1] + b2.y;
                if (MODE == 0) {
                    int which = col / DIMC;
                    int r = col - which * DIMC;
                    int bI = m / NTOK, nI = m - bI * NTOK;
                    int h = r >> 6, d = r & 63;
                    __half* dst;
                    if (which == 0) {
                        float2 c2 = *(const float2*)&g_cq[bI * DIMC + r];
                        v0 += c2.x; v1 += c2.y; dst = g_q;
                    } else if (which == 1) {
                        float2 c2 = *(const float2*)&g_ck[bI * DIMC + r];
                        v0 += c2.x; v1 += c2.y; dst = g_k;
                    } else dst = g_v;
                    *(__half2*)&dst[((size_t)(bI * HEADS + h) * NTOK + nI) * DHEAD + d] =
                        __floats2half2_rn(v0, v1);
                } else if (MODE == 1 || MODE == 3) {
                    size_t ix = (size_t)m * DIMC + col;
                    float2 r2 = *(const float2*)&resid[ix];
                    *(float2*)&out[ix] = make_float2(v0 + r2.x, v1 + r2.y);
                } else { // MODE 2: fast gelu -> half g_ff
                    v0 = fast_gelu(v0);
                    v1 = fast_gelu(v1);
                    *(__half2*)&hout[(size_t)m * FDIM + col] = __floats2half2_rn(v0, v1);
                }
            }
        }
    }
}

// ================= fused attention: 1 CTA per (b,h), 4 q-blocks, fp16 mma =================
#define ATTW 16
#define QH_STR 72
#define KH_STR 72
#define VT_STR 216
#define PH_STR 216
#define AS_STR 212
#define SM_Q  0
#define SM_K  9216
#define SM_VT 39168
#define SM_P  66816
#define SM_S  94464
#define ATT_SMEM 148736

__global__ __launch_bounds__(32 * ATTW, 1) void attn_kernel()
{
    extern __shared__ char sm[];
    const uint32_t sb = smem_u32(sm);
    __half* Qs = (__half*)(sm + SM_Q);
    __half* Ks = (__half*)(sm + SM_K);
    __half* Vt = (__half*)(sm + SM_VT);
    __half* Ps = (__half*)(sm + SM_P);
    float*  Ss = (float*)(sm + SM_S);

    const int tid = threadIdx.x;
    const int wid = tid >> 5, lane = tid & 31;
    const int qr = lane >> 2, qc = lane & 3;
    const int bh = blockIdx.x;
    const int b = bh / HEADS, h = bh - (bh / HEADS) * HEADS;

    const __half* Qg = g_q + (size_t)bh * NTOK * DHEAD;
    const __half* Kg = g_k + (size_t)bh * NTOK * DHEAD;
    const __half* Vg = g_v + (size_t)bh * NTOK * DHEAD;

    // ---- load K (208x64, zero-padded) and V transposed (once per head) ----
    for (int idx = tid; idx < 208 * 8; idx += 32 * ATTW) {
        int r = idx >> 3, c8 = (idx & 7) * 8;
        uint4 v = make_uint4(0u, 0u, 0u, 0u);
        if (r < NTOK) v = *(const uint4*)&Kg[r * DHEAD + c8];
        *(uint4*)&Ks[r * KH_STR + c8] = v;
    }
    for (int idx = tid; idx < 208 * 8; idx += 32 * ATTW) {
        int key = idx >> 3, g = idx & 7, d8 = g * 8;
        __half vals[8];
        uint4 v = make_uint4(0u, 0u, 0u, 0u);
        if (key < NTOK) v = *(const uint4*)&Vg[key * DHEAD + d8];
        *(uint4*)vals = v;
        #pragma unroll
        for (int j = 0; j < 8; j++) {
            int jj = (j + g) & 7;
            Vt[(d8 + jj) * VT_STR + key] = vals[jj];
        }
    }

    const int a_row  = (lane & 15);
    const int a_koff = (lane >> 4) << 3;
    const int b_row  = (lane & 7) + ((lane >> 4) << 3);
    const int b_koff = ((lane >> 3) & 1) << 3;

    for (int blk = 0; blk < 4; blk++) {
        const int m0 = blk * 64;
        // ---- load Q block (64x64) ----
        {
            int r = tid >> 3, c8 = (tid & 7) * 8;
            int gr = m0 + r;
            uint4 v = make_uint4(0u, 0u, 0u, 0u);
            if (gr < NTOK) v = *(const uint4*)&Qg[gr * DHEAD + c8];
            *(uint4*)&Qs[r * QH_STR + c8] = v;
        }
        __syncthreads();    // K/V (first iter) and Q visible; prev PV done

        // ---- S = Q K^T * 0.125 ----
        for (int t = wid; t < 52; t += ATTW) {
            int mt = t & 3, kp = t >> 2;
            float acc0[4] = {0.f, 0.f, 0.f, 0.f};
            float acc1[4] = {0.f, 0.f, 0.f, 0.f};
            #pragma unroll
            for (int ks = 0; ks < 4; ks++) {
                uint32_t a[4], r[4];
                ldsm_x4(a, sb + SM_Q + (uint32_t)((mt * 16 + a_row) * QH_STR + ks * 16 + a_koff) * 2);
                ldsm_x4(r, sb + SM_K + (uint32_t)((kp * 16 + b_row) * KH_STR + ks * 16 + b_koff) * 2);
                uint32_t b0[2] = {r[0], r[1]}, b1[2] = {r[2], r[3]};
                mma_f16(acc0, a, b0);
                mma_f16(acc1, a, b1);
            }
            int r0 = mt * 16 + qr;
            int c0 = kp * 16 + 2 * qc;
            Ss[r0 * AS_STR + c0]            = acc0[0] * 0.125f;
            Ss[r0 * AS_STR + c0 + 1]        = acc0[1] * 0.125f;
            Ss[(r0 + 8) * AS_STR + c0]      = acc0[2] * 0.125f;
            Ss[(r0 + 8) * AS_STR + c0 + 1]  = acc0[3] * 0.125f;
            Ss[r0 * AS_STR + c0 + 8]        = acc1[0] * 0.125f;
            Ss[r0 * AS_STR + c0 + 9]        = acc1[1] * 0.125f;
            Ss[(r0 + 8) * AS_STR + c0 + 8]  = acc1[2] * 0.125f;
            Ss[(r0 + 8) * AS_STR + c0 + 9]  = acc1[3] * 0.125f;
        }
        __syncthreads();

        // ---- row softmax -> P (half) ----
        #pragma unroll
        for (int rr = 0; rr < 4; rr++) {
            int r = wid * 4 + rr;
            float vbuf[7];
            float mx = -1e30f;
            #pragma unroll
            for (int t = 0; t < 7; t++) {
                int col = lane + 32 * t;
                float v = (col < NTOK) ? Ss[r * AS_STR + col] : -1e30f;
                vbuf[t] = v;
                mx = fmaxf(mx, v);
            }
            #pragma unroll
            for (int o = 16; o > 0; o >>= 1)
                mx = fmaxf(mx, __shfl_xor_sync(0xffffffffu, mx, o));
            float sum = 0.f;
            #pragma unroll
            for (int t = 0; t < 7; t++) {
                int col = lane + 32 * t;
                float e = (col < NTOK) ? expf(vbuf[t] - mx) : 0.f;
                vbuf[t] = e;
                sum += e;
            }
            #pragma unroll
            for (int o = 16; o > 0; o >>= 1)
                sum += __shfl_xor_sync(0xffffffffu, sum, o);
            float inv = 1.0f / sum;
            #pragma unroll
            for (int t = 0; t < 7; t++) {
                int col = lane + 32 * t;
                if (col < 208)
                    Ps[r * PH_STR + col] = __float2half_rn((col < NTOK) ? vbuf[t] * inv : 0.f);
            }
        }
        __syncthreads();

        // ---- O = P V : one 16x16 output tile per warp ----
        {
            const int mt = wid & 3, np = wid >> 2;
            float acc0[4] = {0.f, 0.f, 0.f, 0.f};
            float acc1[4] = {0.f, 0.f, 0.f, 0.f};
            #pragma unroll
            for (int ks = 0; ks < 13; ks++) {
                uint32_t a[4], r[4];
                ldsm_x4(a, sb + SM_P  + (uint32_t)((mt * 16 + a_row) * PH_STR + ks * 16 + a_koff) * 2);
                ldsm_x4(r, sb + SM_VT + (uint32_t)((np * 16 + b_row) * VT_STR + ks * 16 + b_koff) * 2);
                uint32_t b0[2] = {r[0], r[1]}, b1[2] = {r[2], r[3]};
                mma_f16(acc0, a, b0);
                mma_f16(acc1, a, b1);
            }
            #pragma unroll
            for (int hf = 0; hf < 2; hf++) {
                int gr = m0 + mt * 16 + qr + hf * 8;
                if (gr < NTOK) {
                    size_t base = (size_t)(b * NTOK + gr) * DIMC + h * DHEAD + np * 16 + 2 * qc;
                    *(__half2*)&g_o[base]     = __floats2half2_rn(acc0[hf * 2], acc0[hf * 2 + 1]);
                    *(__half2*)&g_o[base + 8] = __floats2half2_rn(acc1[hf * 2], acc1[hf * 2 + 1]);
                }
            }
        }
    }
}

// ---------------- layernorm (fp16 output) ----------------
__global__ __launch_bounds__(256) void ln_kernel(const float* __restrict__ x,
                                                 const float* __restrict__ w,
                                                 const float* __restrict__ b,
                                                 __half* __restrict__ out)
{
    int row = blockIdx.x;
    const float* xr = x + (size_t)row * DIMC;
    float s = 0.f, s2 = 0.f;
    float vals[3];
    #pragma unroll
    for (int t = 0; t < 3; t++) {
        float v = xr[threadIdx.x + 256 * t];
        vals[t] = v; s += v; s2 += v * v;
    }
    __shared__ float shs[8], shs2[8];
    #pragma unroll
    for (int o = 16; o > 0; o >>= 1) {
        s  += __shfl_down_sync(0xffffffffu, s,  o);
        s2 += __shfl_down_sync(0xffffffffu, s2, o);
    }
    if ((threadIdx.x & 31) == 0) { shs[threadIdx.x >> 5] = s; shs2[threadIdx.x >> 5] = s2; }
    __syncthreads();
    __shared__ float sh_mean, sh_rstd;
    if (threadIdx.x == 0) {
        float ts = 0.f, ts2 = 0.f;
        #pragma unroll
        for (int i = 0; i < 8; i++) { ts += shs[i]; ts2 += shs2[i]; }
        float mean = ts / DIMC;
        float var  = ts2 / DIMC - mean * mean;
        sh_mean = mean;
        sh_rstd = rsqrtf(var + EPSLN);
    }
    __syncthreads();
    float mean = sh_mean, rstd = sh_rstd;
    __half* orow = out + (size_t)row * DIMC;
    #pragma unroll
    for (int t = 0; t < 3; t++) {
        int i = threadIdx.x + 256 * t;
        orow[i] = __float2half_rn((vals[t] - mean) * rstd * w[i] + b[i]);
    }
}

// ---------------- conv1d (temporal calibration), warp per output ----------------
__global__ __launch_bounds__(256) void conv_kernel(const float* __restrict__ wq,
                                                   const float* __restrict__ bq,
                                                   const float* __restrict__ wk,
                                                   const float* __restrict__ bk)
{
    int gw   = blockIdx.x * 8 + (threadIdx.x >> 5);
    int lane = threadIdx.x & 31;
    int which = gw / (BATCH * DIMC);
    int rem   = gw % (BATCH * DIMC);
    int bt = rem / DIMC;
    int co = rem % DIMC;
    int bv = bt >> 2, t = bt & 3;
    const float* w  = which ? wk : wq;
    const float* bb = which ? bk : bq;
    float s = 0.f;
    const __half* h0 = (t > 0) ? (g_h + (size_t)(bv * 4 + t - 1) * NTOK * DIMC) : nullptr;
    const __half* h1 = g_h + (size_t)(bv * 4 + t) * NTOK * DIMC;
    const __half* h2 = (t < 3) ? (g_h + (size_t)(bv * 4 + t + 1) * NTOK * DIMC) : nullptr;
    for (int ci = lane; ci < DIMC; ci += 32) {
        const float* wp = w + ((size_t)co * DIMC + ci) * 3;
        float w0 = wp[0], w1 = wp[1], w2 = wp[2];
        if (h0) s += w0 * __half2float(h0[ci]);
        s += w1 * __half2float(h1[ci]);
        if (h2) s += w2 * __half2float(h2[ci]);
    }
    #pragma unroll
    for (int o = 16; o > 0; o >>= 1) s += __shfl_down_sync(0xffffffffu, s, o);
    if (lane == 0) {
        float* dst = which ? g_ck : g_cq;
        dst[bt * DIMC + co] = s + bb[co];
    }
}

// ---------------- launch ----------------
extern "C" void kernel_launch(void* const* d_in, const int* in_sizes, int n_in,
                              void* d_out, int out_size)
{
    const float* x      = (const float*)d_in[0];
    const float* ln1_w  = (const float*)d_in[1];
    const float* ln1_b  = (const float*)d_in[2];
    const float* qkv_w  = (const float*)d_in[3];
    const float* qkv_b  = (const float*)d_in[4];
    const float* convq_w= (const float*)d_in[5];
    const float* convq_b= (const float*)d_in[6];
    const float* convk_w= (const float*)d_in[7];
    const float* convk_b= (const float*)d_in[8];
    const float* proj_w = (const float*)d_in[9];
    const float* proj_b = (const float*)d_in[10];
    const float* ln2_w  = (const float*)d_in[11];
    const float* ln2_b  = (const float*)d_in[12];
    const float* ff1_w  = (const float*)d_in[13];
    const float* ff1_b  = (const float*)d_in[14];
    const float* ff2_w  = (const float*)d_in[15];
    const float* ff2_b  = (const float*)d_in[16];
    float* out = (float*)d_out;

    __half* p_h;  cudaGetSymbolAddress((void**)&p_h,  g_h);
    __half* p_o;  cudaGetSymbolAddress((void**)&p_o,  g_o);
    float*  p_x1; cudaGetSymbolAddress((void**)&p_x1, g_x1);
    __half* p_ff; cudaGetSymbolAddress((void**)&p_ff, g_ff);
    __half* p_w;  cudaGetSymbolAddress((void**)&p_w,  g_wts);

    cudaFuncSetAttribute(tc_gemm<0>, cudaFuncAttributeMaxDynamicSharedMemorySize, TC_SMEM);
    cudaFuncSetAttribute(tc_gemm<1>, cudaFuncAttributeMaxDynamicSharedMemorySize, TC_SMEM);
    cudaFuncSetAttribute(tc_gemm<2>, cudaFuncAttributeMaxDynamicSharedMemorySize, TC_SMEM);
    cudaFuncSetAttribute(tc_gemm<3>, cudaFuncAttributeMaxDynamicSharedMemorySize, TC_SMEM);
    cudaFuncSetAttribute(attn_kernel, cudaFuncAttributeMaxDynamicSharedMemorySize, ATT_SMEM);

    const int MT = (MROWS + TBM - 1) / TBM;   // 99

    // 0. pre-convert all weights to fp16 (single launch)
    round_all_kernel<<<(N4_TOT + 255) / 256, 256>>>(qkv_w, proj_w, ff1_w, ff2_w, p_w);
    // 1. LN1 -> half g_h
    ln_kernel<<<MROWS, 256>>>(x, ln1_w, ln1_b, p_h);
    // 2. temporal conv on per-frame CLS tokens
    conv_kernel<<<(2 * BATCH * DIMC) / 8, 256>>>(convq_w, convq_b, convk_w, convk_b);
    // 3. QKV GEMM + scatter (+cq/ck) -> half q/k/v
    tc_gemm<0><<<dim3(3 * DIMC / TBN, MT), NTHR, TC_SMEM>>>(
        p_h, p_w + W_QKV_OFF, qkv_b, nullptr, nullptr, nullptr, MROWS, DIMC);
    // 4. fused fp16 attention (1 CTA per head) -> half g_o
    attn_kernel<<<BATCH * HEADS, 32 * ATTW, ATT_SMEM>>>();
    // 5. proj + residual -> fp32 g_x1
    tc_gemm<1><<<dim3(DIMC / TBN, MT), NTHR, TC_SMEM>>>(
        p_o, p_w + W_PROJ_OFF, proj_b, x, p_x1, nullptr, MROWS, DIMC);
    // 6. LN2 -> half g_h
    ln_kernel<<<MROWS, 256>>>(p_x1, ln2_w, ln2_b, p_h);
    // 7. FF1 + fast GELU -> half g_ff
    tc_gemm<2><<<dim3(FDIM / TBN, MT), NTHR, TC_SMEM>>>(
        p_h, p_w + W_FF1_OFF, ff1_b, nullptr, nullptr, p_ff, MROWS, DIMC);
    // 8. FF2 + residual -> fp32 out
    tc_gemm<3><<<dim3(DIMC / TBN, MT), NTHR, TC_SMEM>>>(
        p_ff, p_w + W_FF2_OFF, ff2_b, p_x1, out, nullptr, MROWS, FDIM);
}

// round 15
// speedup vs baseline: 1.3008x; 1.0829x over previous
#include <cuda_runtime.h>
#include <cuda_fp16.h>
#include <math.h>
#include <stdint.h>

// ---------------- problem constants ----------------
#define BATCH   64
#define NTOK    197
#define DIMC    768
#define HEADS   12
#define DHEAD   64
#define MROWS   (BATCH * NTOK)          // 12608
#define FDIM    (DIMC * 4)              // 3072
#define EPSLN   1e-6f

#define W_QKV_OFF  0
#define W_PROJ_OFF (3 * DIMC * DIMC)
#define W_FF1_OFF  (W_PROJ_OFF + DIMC * DIMC)
#define W_FF2_OFF  (W_FF1_OFF + FDIM * DIMC)
#define W_TOTAL    (W_FF2_OFF + DIMC * FDIM)

// ---------------- scratch (device globals, no allocation) ----------------
__device__ __half g_h  [MROWS * DIMC];                 // LN out (fp16)
__device__ __half g_q  [BATCH * HEADS * NTOK * DHEAD]; // q + cq (fp16)
__device__ __half g_k  [BATCH * HEADS * NTOK * DHEAD];
__device__ __half g_v  [BATCH * HEADS * NTOK * DHEAD];
__device__ float  g_cq [BATCH * DIMC];
__device__ float  g_ck [BATCH * DIMC];
__device__ __half g_o  [MROWS * DIMC];                 // attn out (fp16)
__device__ float  g_x1 [MROWS * DIMC];                 // x + attn branch (fp32)
__device__ __half g_ff [MROWS * FDIM];                 // gelu(ff1) (fp16)
__device__ __half g_wts[W_TOTAL];                      // fp16 weights

// ================= helpers =================
__device__ __forceinline__ void mma_f16(float* d, const uint32_t* a, const uint32_t* b) {
    asm volatile(
        "mma.sync.aligned.m16n8k16.row.col.f32.f16.f16.f32 "
        "{%0,%1,%2,%3}, {%4,%5,%6,%7}, {%8,%9}, {%0,%1,%2,%3};"
        : "+f"(d[0]), "+f"(d[1]), "+f"(d[2]), "+f"(d[3])
        : "r"(a[0]), "r"(a[1]), "r"(a[2]), "r"(a[3]), "r"(b[0]), "r"(b[1]));
}
__device__ __forceinline__ void ldsm_x4(uint32_t* r, uint32_t addr) {
    asm volatile("ldmatrix.sync.aligned.m8n8.x4.shared.b16 {%0,%1,%2,%3}, [%4];"
                 : "=r"(r[0]), "=r"(r[1]), "=r"(r[2]), "=r"(r[3]) : "r"(addr));
}
__device__ __forceinline__ uint32_t smem_u32(const void* p) {
    uint32_t a;
    asm("{ .reg .u64 t; cvta.to.shared.u64 t, %1; cvt.u32.u64 %0, t; }" : "=r"(a) : "l"(p));
    return a;
}
__device__ __forceinline__ void cpa16(uint32_t dst, const void* src, int sz) {
    asm volatile("cp.async.cg.shared.global [%0], [%1], 16, %2;" :: "r"(dst), "l"(src), "r"(sz));
}
#define CP_COMMIT asm volatile("cp.async.commit_group;" ::: "memory")
#define CP_WAIT0  asm volatile("cp.async.wait_group 0;" ::: "memory")

// fast exact-GELU via Abramowitz-Stegun 7.1.26 erf (|abs err| <= 1.5e-7)
__device__ __forceinline__ float fast_gelu(float v) {
    float z = fabsf(v) * 0.70710678118654752f;
    float t = __fdividef(1.0f, fmaf(0.3275911f, z, 1.0f));
    float poly = t * fmaf(t, fmaf(t, fmaf(t, fmaf(t, 1.061405429f, -1.453152027f),
                         1.421413741f), -0.284496736f), 0.254829592f);
    float er = 1.0f - poly * __expf(-z * z);
    er = copysignf(er, v);
    return 0.5f * v * (1.0f + er);
}

// ================= merged weight pre-conversion fp32 -> fp16 =================
#define N4_QKV  (3 * DIMC * DIMC / 4)
#define N4_PROJ (DIMC * DIMC / 4)
#define N4_FF1  (FDIM * DIMC / 4)
#define N4_TOT  (W_TOTAL / 4)
__global__ __launch_bounds__(256) void round_all_kernel(const float* __restrict__ qkv,
                                                        const float* __restrict__ proj,
                                                        const float* __restrict__ ff1,
                                                        const float* __restrict__ ff2,
                                                        __half* __restrict__ dst)
{
    int i = blockIdx.x * 256 + threadIdx.x;
    if (i >= N4_TOT) return;
    const float* src;
    int j = i;
    if (j < N4_QKV) src = qkv;
    else if ((j -= N4_QKV) < N4_PROJ) src = proj;
    else if ((j -= N4_PROJ) < N4_FF1) src = ff1;
    else { j -= N4_FF1; src = ff2; }
    float4 v = ((const float4*)src)[j];
    ((__half2*)dst)[2 * i]     = __floats2half2_rn(v.x, v.y);
    ((__half2*)dst)[2 * i + 1] = __floats2half2_rn(v.z, v.w);
}

// ==== fp16 mma GEMM, 128x128 tile, 512 thr (16 warps, 32x32 warp tile), 2-stage, 2 CTAs/SM ====
// MODE 0: QKV scatter (+cq/ck) -> half q/k/v, MODE 1: proj + resid -> fp32,
// MODE 2: ff1 + gelu -> half g_ff, MODE 3: ff2 + resid -> fp32 out
#define TBM 128
#define TBN 128
#define TBK 64
#define NTHR 512
#define HPAD 72
#define ABUF_A (TBM * HPAD * 2)          // 18432 B
#define ABUF_B (TBN * HPAD * 2)          // 18432 B
#define STG_BYTES (ABUF_A + ABUF_B)      // 36864 B
#define TC_SMEM (2 * STG_BYTES)          // 73728 B -> 2 CTAs/SM, 32 warps/SM

template<int MODE>
__global__ __launch_bounds__(NTHR, 2)
void tc_gemm(const __half* __restrict__ A, const __half* __restrict__ W,
             const float* __restrict__ bias, const float* __restrict__ resid,
             float* __restrict__ out, __half* __restrict__ hout, int M, int K)
{
    extern __shared__ char smem[];
    const uint32_t sb32 = smem_u32(smem);
    const int tid = threadIdx.x;
    const int wid = tid >> 5, lane = tid & 31;
    const int qr = lane >> 2, qc = lane & 3;
    const int wm = wid >> 2, wn = wid & 3;          // 4 x 4 warp grid, 32x32 warp tiles
    const int m0 = blockIdx.y * TBM, n0 = blockIdx.x * TBN;

    const int sr  = tid >> 2;            // 0..127
    const int sub = tid & 3;             // 16 halves = 2x16B
    const int aok = ((m0 + sr) < M) ? 16 : 0;
    const __half* ap = A + (size_t)(m0 + sr) * K + sub * 16;
    const uint32_t da = sb32 + (sr * HPAD + sub * 16) * 2;
    const __half* bp = W + (size_t)(n0 + sr) * K + sub * 16;
    const uint32_t db = sb32 + ABUF_A + (sr * HPAD + sub * 16) * 2;

    const int a_row  = (lane & 15);
    const int a_koff = (lane >> 4) << 3;
    const int b_row  = (lane & 7) + ((lane >> 4) << 3);
    const int b_koff = ((lane >> 3) & 1) << 3;
    uint32_t aoff[2], boff[2];
    #pragma unroll
    for (int mt = 0; mt < 2; mt++)
        aoff[mt] = ((wm * 32 + mt * 16 + a_row) * HPAD + a_koff) * 2;
    #pragma unroll
    for (int np = 0; np < 2; np++)
        boff[np] = ABUF_A + ((wn * 32 + np * 16 + b_row) * HPAD + b_koff) * 2;

    float acc[2][4][4];
    #pragma unroll
    for (int i = 0; i < 2; i++)
        #pragma unroll
        for (int j = 0; j < 4; j++)
            #pragma unroll
            for (int t = 0; t < 4; t++) acc[i][j][t] = 0.f;

    const int NC = K / TBK;

    #pragma unroll
    for (int q = 0; q < 2; q++) {
        cpa16(da + q * 16, ap + q * 8, aok);
        cpa16(db + q * 16, bp + q * 8, 16);
    }
    CP_COMMIT;

    for (int c = 0; c < NC; c++) {
        CP_WAIT0;
        __syncthreads();
        if (c + 1 < NC) {
            const uint32_t so = ((c + 1) & 1) * STG_BYTES;
            const int kk = (c + 1) * TBK;
            #pragma unroll
            for (int q = 0; q < 2; q++) {
                cpa16(da + so + q * 16, ap + kk + q * 8, aok);
                cpa16(db + so + q * 16, bp + kk + q * 8, 16);
            }
            CP_COMMIT;
        }

        const uint32_t sbase = sb32 + (c & 1) * STG_BYTES;
        #pragma unroll
        for (int ks = 0; ks < 4; ks++) {
            const uint32_t kb = sbase + (ks * 16) * 2;
            uint32_t afr[2][4], bfr[4][2];
            #pragma unroll
            for (int mt = 0; mt < 2; mt++)
                ldsm_x4(afr[mt], kb + aoff[mt]);
            #pragma unroll
            for (int np = 0; np < 2; np++) {
                uint32_t r[4];
                ldsm_x4(r, kb + boff[np]);
                bfr[2 * np][0] = r[0]; bfr[2 * np][1] = r[1];
                bfr[2 * np + 1][0] = r[2]; bfr[2 * np + 1][1] = r[3];
            }
            #pragma unroll
            for (int mt = 0; mt < 2; mt++)
                #pragma unroll
                for (int nt = 0; nt < 4; nt++)
                    mma_f16(acc[mt][nt], afr[mt], bfr[nt]);
        }
    }

    // ---- epilogue: fused stores ----
    #pragma unroll
    for (int mt = 0; mt < 2; mt++) {
        int mA = m0 + wm * 32 + mt * 16 + qr;
        #pragma unroll
        for (int nt = 0; nt < 4; nt++) {
            int col = n0 + wn * 32 + nt * 8 + 2 * qc;
            float2 b2 = *(const float2*)&bias[col];
            #pragma unroll
            for (int half = 0; half < 2; half++) {
                int m = mA + half * 8;
                if (m >= M) continue;
                float v0 = acc[mt][nt][half * 2 + 0] + b2.x;
                float v1 = acc[mt][nt][half * 2 + 1] + b2.y;
                if (MODE == 0) {
                    int which = col / DIMC;
                    int r = col - which * DIMC;
                    int bI = m / NTOK, nI = m - bI * NTOK;
                    int h = r >> 6, d = r & 63;
                    __half* dst;
                    if (which == 0) {
                        float2 c2 = *(const float2*)&g_cq[bI * DIMC + r];
                        v0 += c2.x; v1 += c2.y; dst = g_q;
                    } else if (which == 1) {
                        float2 c2 = *(const float2*)&g_ck[bI * DIMC + r];
                        v0 += c2.x; v1 += c2.y; dst = g_k;
                    } else dst = g_v;
                    *(__half2*)&dst[((size_t)(bI * HEADS + h) * NTOK + nI) * DHEAD + d] =
                        __floats2half2_rn(v0, v1);
                } else if (MODE == 1 || MODE == 3) {
                    size_t ix = (size_t)m * DIMC + col;
                    float2 r2 = *(const float2*)&resid[ix];
                    *(float2*)&out[ix] = make_float2(v0 + r2.x, v1 + r2.y);
                } else { // MODE 2: fast gelu -> half g_ff
                    v0 = fast_gelu(v0);
                    v1 = fast_gelu(v1);
                    *(__half2*)&hout[(size_t)m * FDIM + col] = __floats2half2_rn(v0, v1);
                }
            }
        }
    }
}

// ===== fused attention: 1 CTA per (b,h), 4 q-blocks, fp16 mma, S stored half -> 2 CTAs/SM =====
#define ATTW 16
#define QH_STR 72
#define KH_STR 72
#define VT_STR 216
#define PH_STR 216
#define SM_Q  0
#define SM_K  9216
#define SM_VT 39168
#define SM_P  66816
#define ATT_SMEM 94464                     // -> 2 CTAs/SM

__global__ __launch_bounds__(32 * ATTW, 2) void attn_kernel()
{
    extern __shared__ char sm[];
    const uint32_t sb = smem_u32(sm);
    __half* Qs = (__half*)(sm + SM_Q);
    __half* Ks = (__half*)(sm + SM_K);
    __half* Vt = (__half*)(sm + SM_VT);
    __half* Ps = (__half*)(sm + SM_P);

    const int tid = threadIdx.x;
    const int wid = tid >> 5, lane = tid & 31;
    const int qr = lane >> 2, qc = lane & 3;
    const int bh = blockIdx.x;
    const int b = bh / HEADS, h = bh - (bh / HEADS) * HEADS;

    const __half* Qg = g_q + (size_t)bh * NTOK * DHEAD;
    const __half* Kg = g_k + (size_t)bh * NTOK * DHEAD;
    const __half* Vg = g_v + (size_t)bh * NTOK * DHEAD;

    // ---- load K (208x64, zero-padded) and V transposed (once per head) ----
    for (int idx = tid; idx < 208 * 8; idx += 32 * ATTW) {
        int r = idx >> 3, c8 = (idx & 7) * 8;
        uint4 v = make_uint4(0u, 0u, 0u, 0u);
        if (r < NTOK) v = *(const uint4*)&Kg[r * DHEAD + c8];
        *(uint4*)&Ks[r * KH_STR + c8] = v;
    }
    for (int idx = tid; idx < 208 * 8; idx += 32 * ATTW) {
        int key = idx >> 3, g = idx & 7, d8 = g * 8;
        __half vals[8];
        uint4 v = make_uint4(0u, 0u, 0u, 0u);
        if (key < NTOK) v = *(const uint4*)&Vg[key * DHEAD + d8];
        *(uint4*)vals = v;
        #pragma unroll
        for (int j = 0; j < 8; j++) {
            int jj = (j + g) & 7;
            Vt[(d8 + jj) * VT_STR + key] = vals[jj];
        }
    }

    const int a_row  = (lane & 15);
    const int a_koff = (lane >> 4) << 3;
    const int b_row  = (lane & 7) + ((lane >> 4) << 3);
    const int b_koff = ((lane >> 3) & 1) << 3;

    for (int blk = 0; blk < 4; blk++) {
        const int m0 = blk * 64;
        // ---- load Q block (64x64) ----
        {
            int r = tid >> 3, c8 = (tid & 7) * 8;
            int gr = m0 + r;
            uint4 v = make_uint4(0u, 0u, 0u, 0u);
            if (gr < NTOK) v = *(const uint4*)&Qg[gr * DHEAD + c8];
            *(uint4*)&Qs[r * QH_STR + c8] = v;
        }
        __syncthreads();    // K/V (first iter) and Q visible; prev PV done

        // ---- S = Q K^T * 0.125 -> half, stored into Ps ----
        for (int t = wid; t < 52; t += ATTW) {
            int mt = t & 3, kp = t >> 2;
            float acc0[4] = {0.f, 0.f, 0.f, 0.f};
            float acc1[4] = {0.f, 0.f, 0.f, 0.f};
            #pragma unroll
            for (int ks = 0; ks < 4; ks++) {
                uint32_t a[4], r[4];
                ldsm_x4(a, sb + SM_Q + (uint32_t)((mt * 16 + a_row) * QH_STR + ks * 16 + a_koff) * 2);
                ldsm_x4(r, sb + SM_K + (uint32_t)((kp * 16 + b_row) * KH_STR + ks * 16 + b_koff) * 2);
                uint32_t b0[2] = {r[0], r[1]}, b1[2] = {r[2], r[3]};
                mma_f16(acc0, a, b0);
                mma_f16(acc1, a, b1);
            }
            int r0 = mt * 16 + qr;
            int c0 = kp * 16 + 2 * qc;
            *(__half2*)&Ps[r0 * PH_STR + c0]           = __floats2half2_rn(acc0[0] * 0.125f, acc0[1] * 0.125f);
            *(__half2*)&Ps[(r0 + 8) * PH_STR + c0]     = __floats2half2_rn(acc0[2] * 0.125f, acc0[3] * 0.125f);
            *(__half2*)&Ps[r0 * PH_STR + c0 + 8]       = __floats2half2_rn(acc1[0] * 0.125f, acc1[1] * 0.125f);
            *(__half2*)&Ps[(r0 + 8) * PH_STR + c0 + 8] = __floats2half2_rn(acc1[2] * 0.125f, acc1[3] * 0.125f);
        }
        __syncthreads();

        // ---- row softmax in-place on Ps (fp32 math) ----
        #pragma unroll
        for (int rr = 0; rr < 4; rr++) {
            int r = wid * 4 + rr;
            float vbuf[7];
            float mx = -1e30f;
            #pragma unroll
            for (int t = 0; t < 7; t++) {
                int col = lane + 32 * t;
                float v = (col < NTOK) ? __half2float(Ps[r * PH_STR + col]) : -1e30f;
                vbuf[t] = v;
                mx = fmaxf(mx, v);
            }
            #pragma unroll
            for (int o = 16; o > 0; o >>= 1)
                mx = fmaxf(mx, __shfl_xor_sync(0xffffffffu, mx, o));
            float sum = 0.f;
            #pragma unroll
            for (int t = 0; t < 7; t++) {
                int col = lane + 32 * t;
                float e = (col < NTOK) ? expf(vbuf[t] - mx) : 0.f;
                vbuf[t] = e;
                sum += e;
            }
            #pragma unroll
            for (int o = 16; o > 0; o >>= 1)
                sum += __shfl_xor_sync(0xffffffffu, sum, o);
            float inv = 1.0f / sum;
            #pragma unroll
            for (int t = 0; t < 7; t++) {
                int col = lane + 32 * t;
                if (col < 208)
                    Ps[r * PH_STR + col] = __float2half_rn((col < NTOK) ? vbuf[t] * inv : 0.f);
            }
        }
        __syncthreads();

        // ---- O = P V : one 16x16 output tile per warp ----
        {
            const int mt = wid & 3, np = wid >> 2;
            float acc0[4] = {0.f, 0.f, 0.f, 0.f};
            float acc1[4] = {0.f, 0.f, 0.f, 0.f};
            #pragma unroll
            for (int ks = 0; ks < 13; ks++) {
                uint32_t a[4], r[4];
                ldsm_x4(a, sb + SM_P  + (uint32_t)((mt * 16 + a_row) * PH_STR + ks * 16 + a_koff) * 2);
                ldsm_x4(r, sb + SM_VT + (uint32_t)((np * 16 + b_row) * VT_STR + ks * 16 + b_koff) * 2);
                uint32_t b0[2] = {r[0], r[1]}, b1[2] = {r[2], r[3]};
                mma_f16(acc0, a, b0);
                mma_f16(acc1, a, b1);
            }
            #pragma unroll
            for (int hf = 0; hf < 2; hf++) {
                int gr = m0 + mt * 16 + qr + hf * 8;
                if (gr < NTOK) {
                    size_t base = (size_t)(b * NTOK + gr) * DIMC + h * DHEAD + np * 16 + 2 * qc;
                    *(__half2*)&g_o[base]     = __floats2half2_rn(acc0[hf * 2], acc0[hf * 2 + 1]);
                    *(__half2*)&g_o[base + 8] = __floats2half2_rn(acc1[hf * 2], acc1[hf * 2 + 1]);
                }
            }
        }
    }
}

// ---------------- layernorm (fp16 output) ----------------
__global__ __launch_bounds__(256) void ln_kernel(const float* __restrict__ x,
                                                 const float* __restrict__ w,
                                                 const float* __restrict__ b,
                                                 __half* __restrict__ out)
{
    int row = blockIdx.x;
    const float* xr = x + (size_t)row * DIMC;
    float s = 0.f, s2 = 0.f;
    float vals[3];
    #pragma unroll
    for (int t = 0; t < 3; t++) {
        float v = xr[threadIdx.x + 256 * t];
        vals[t] = v; s += v; s2 += v * v;
    }
    __shared__ float shs[8], shs2[8];
    #pragma unroll
    for (int o = 16; o > 0; o >>= 1) {
        s  += __shfl_down_sync(0xffffffffu, s,  o);
        s2 += __shfl_down_sync(0xffffffffu, s2, o);
    }
    if ((threadIdx.x & 31) == 0) { shs[threadIdx.x >> 5] = s; shs2[threadIdx.x >> 5] = s2; }
    __syncthreads();
    __shared__ float sh_mean, sh_rstd;
    if (threadIdx.x == 0) {
        float ts = 0.f, ts2 = 0.f;
        #pragma unroll
        for (int i = 0; i < 8; i++) { ts += shs[i]; ts2 += shs2[i]; }
        float mean = ts / DIMC;
        float var  = ts2 / DIMC - mean * mean;
        sh_mean = mean;
        sh_rstd = rsqrtf(var + EPSLN);
    }
    __syncthreads();
    float mean = sh_mean, rstd = sh_rstd;
    __half* orow = out + (size_t)row * DIMC;
    #pragma unroll
    for (int t = 0; t < 3; t++) {
        int i = threadIdx.x + 256 * t;
        orow[i] = __float2half_rn((vals[t] - mean) * rstd * w[i] + b[i]);
    }
}

// ------- conv1d v2: warp = (which, 4 co, 8 bt) register-blocked, weight/h reuse -------
__global__ __launch_bounds__(256) void conv_kernel(const float* __restrict__ wq,
                                                   const float* __restrict__ bq,
                                                   const float* __restrict__ wk,
                                                   const float* __restrict__ bk)
{
    int gw   = blockIdx.x * 8 + (threadIdx.x >> 5);   // 0..3071
    int lane = threadIdx.x & 31;
    int which = gw / 1536;
    int rem   = gw - which * 1536;       // 192 co-blocks x 8 bt-blocks
    int co4   = rem >> 3;                // 0..191 (block of 4 co)
    int btb   = rem & 7;                 // 0..7 (block of 8 bt)
    const float* w  = which ? wk : wq;
    const float* bb = which ? bk : bq;

    float acc[4][8];
    #pragma unroll
    for (int c = 0; c < 4; c++)
        #pragma unroll
        for (int j = 0; j < 8; j++) acc[c][j] = 0.f;

    const int HSTRIDE = NTOK * DIMC;
    for (int ci0 = 0; ci0 < DIMC; ci0 += 32) {
        int ci = ci0 + lane;
        float w0[4], w1[4], w2[4];
        #pragma unroll
        for (int c = 0; c < 4; c++) {
            const float* wp = w + ((size_t)(co4 * 4 + c) * DIMC + ci) * 3;
            w0[c] = wp[0]; w1[c] = wp[1]; w2[c] = wp[2];
        }
        #pragma unroll
        for (int j = 0; j < 8; j++) {     // t = (btb*8+j)&3 = j&3 (8 % 4 == 0)
            int bt = btb * 8 + j;
            const __half* hb = g_h + (size_t)bt * HSTRIDE + ci;
            float hc = __half2float(hb[0]);
            float hp = 0.f, hn = 0.f;
            if ((j & 3) > 0) hp = __half2float(hb[-HSTRIDE]);
            if ((j & 3) < 3) hn = __half2float(hb[HSTRIDE]);
            #pragma unroll
            for (int c = 0; c < 4; c++)
                acc[c][j] += w0[c] * hp + w1[c] * hc + w2[c] * hn;
        }
    }
    #pragma unroll
    for (int c = 0; c < 4; c++)
        #pragma unroll
        for (int j = 0; j < 8; j++) {
            float s = acc[c][j];
            #pragma unroll
            for (int o = 16; o > 0; o >>= 1) s += __shfl_down_sync(0xffffffffu, s, o);
            if (lane == 0) {
                int bt = btb * 8 + j;
                int co = co4 * 4 + c;
                float* dst = which ? g_ck : g_cq;
                dst[bt * DIMC + co] = s + bb[co];
            }
        }
}

// ---------------- launch ----------------
extern "C" void kernel_launch(void* const* d_in, const int* in_sizes, int n_in,
                              void* d_out, int out_size)
{
    const float* x      = (const float*)d_in[0];
    const float* ln1_w  = (const float*)d_in[1];
    const float* ln1_b  = (const float*)d_in[2];
    const float* qkv_w  = (const float*)d_in[3];
    const float* qkv_b  = (const float*)d_in[4];
    const float* convq_w= (const float*)d_in[5];
    const float* convq_b= (const float*)d_in[6];
    const float* convk_w= (const float*)d_in[7];
    const float* convk_b= (const float*)d_in[8];
    const float* proj_w = (const float*)d_in[9];
    const float* proj_b = (const float*)d_in[10];
    const float* ln2_w  = (const float*)d_in[11];
    const float* ln2_b  = (const float*)d_in[12];
    const float* ff1_w  = (const float*)d_in[13];
    const float* ff1_b  = (const float*)d_in[14];
    const float* ff2_w  = (const float*)d_in[15];
    const float* ff2_b  = (const float*)d_in[16];
    float* out = (float*)d_out;

    __half* p_h;  cudaGetSymbolAddress((void**)&p_h,  g_h);
    __half* p_o;  cudaGetSymbolAddress((void**)&p_o,  g_o);
    float*  p_x1; cudaGetSymbolAddress((void**)&p_x1, g_x1);
    __half* p_ff; cudaGetSymbolAddress((void**)&p_ff, g_ff);
    __half* p_w;  cudaGetSymbolAddress((void**)&p_w,  g_wts);

    cudaFuncSetAttribute(tc_gemm<0>, cudaFuncAttributeMaxDynamicSharedMemorySize, TC_SMEM);
    cudaFuncSetAttribute(tc_gemm<1>, cudaFuncAttributeMaxDynamicSharedMemorySize, TC_SMEM);
    cudaFuncSetAttribute(tc_gemm<2>, cudaFuncAttributeMaxDynamicSharedMemorySize, TC_SMEM);
    cudaFuncSetAttribute(tc_gemm<3>, cudaFuncAttributeMaxDynamicSharedMemorySize, TC_SMEM);
    cudaFuncSetAttribute(attn_kernel, cudaFuncAttributeMaxDynamicSharedMemorySize, ATT_SMEM);

    const int MT = (MROWS + TBM - 1) / TBM;   // 99

    // 0. pre-convert all weights to fp16 (single launch)
    round_all_kernel<<<(N4_TOT + 255) / 256, 256>>>(qkv_w, proj_w, ff1_w, ff2_w, p_w);
    // 1. LN1 -> half g_h
    ln_kernel<<<MROWS, 256>>>(x, ln1_w, ln1_b, p_h);
    // 2. temporal conv (register-blocked) on per-frame CLS tokens
    conv_kernel<<<384, 256>>>(convq_w, convq_b, convk_w, convk_b);
    // 3. QKV GEMM + scatter (+cq/ck) -> half q/k/v
    tc_gemm<0><<<dim3(3 * DIMC / TBN, MT), NTHR, TC_SMEM>>>(
        p_h, p_w + W_QKV_OFF, qkv_b, nullptr, nullptr, nullptr, MROWS, DIMC);
    // 4. fused fp16 attention (1 CTA per head, 2 CTAs/SM) -> half g_o
    attn_kernel<<<BATCH * HEADS, 32 * ATTW, ATT_SMEM>>>();
    // 5. proj + residual -> fp32 g_x1
    tc_gemm<1><<<dim3(DIMC / TBN, MT), NTHR, TC_SMEM>>>(
        p_o, p_w + W_PROJ_OFF, proj_b, x, p_x1, nullptr, MROWS, DIMC);
    // 6. LN2 -> half g_h
    ln_kernel<<<MROWS, 256>>>(p_x1, ln2_w, ln2_b, p_h);
    // 7. FF1 + fast GELU -> half g_ff
    tc_gemm<2><<<dim3(FDIM / TBN, MT), NTHR, TC_SMEM>>>(
        p_h, p_w + W_FF1_OFF, ff1_b, nullptr, nullptr, p_ff, MROWS, DIMC);
    // 8. FF2 + residual -> fp32 out
    tc_gemm<3><<<dim3(DIMC / TBN, MT), NTHR, TC_SMEM>>>(
        p_ff, p_w + W_FF2_OFF, ff2_b, p_x1, out, nullptr, MROWS, FDIM);
}